// round 6
// baseline (speedup 1.0000x reference)
#include <cuda_runtime.h>
#include <math.h>

#define BB   4
#define NN   50000
#define CC   64
#define EE   800000
#define NLBL 10000
#define RR   (NN*BB)        /* 200000 GEMM rows (node,batch) */
#define ROWF (BB*CC)        /* 256 floats per node across batches */
#define NTILES (RR/32)      /* 6250 */

// packed fp32x2 helpers (Blackwell FFMA2 path — ptxas never emits this from C++)
#define FMA2(acc, a, b) asm("fma.rn.f32x2 %0, %1, %2, %0;" : "+l"(acc) : "l"(a), "l"(b))
#define PACK2BC(d, f)   asm("mov.b64 %0, {%1, %1};" : "=l"(d) : "r"(__float_as_uint(f)))
#define UNPACK2(lo, hi, v) do { unsigned _ulo, _uhi; \
    asm("mov.b64 {%0, %1}, %2;" : "=r"(_ulo), "=r"(_uhi) : "l"(v)); \
    lo = __uint_as_float(_ulo); hi = __uint_as_float(_uhi); } while (0)

// ---------------- device scratch (no allocations allowed) ----------------
__device__ float g_X[2][RR*CC];     // ping-pong node state, 2 x 51.2MB
__device__ float g_X0[RR*CC];       // initial features (needed for attention)
__device__ float g_AGG[RR*CC];      // neighbor sums
__device__ float g_P[5*64*192];     // P[l] = ggc[l] @ w_ih^T, [k][j] layout
__device__ float g_WHH[64*192];     // w_hh^T, [k][j]
__device__ float g_AIW[128*128];    // ai_w^T, [k][j]
__device__ float g_AJW[128*128];    // aj_w^T, [k][j]
__device__ float g_POOL[512];       // att pooled sums [b][128]
// CSR by destination
__device__ int   g_cnt[NN];
__device__ int   g_off[NN];
__device__ int   g_cur[NN];
__device__ int   g_csr[EE];

__device__ __forceinline__ float sigm(float v) { return 1.0f / (1.0f + expf(-v)); }

// ---------------- prep kernels ----------------
__global__ void k_prep_P(const float* __restrict__ ggc, const float* __restrict__ w_ih) {
    int idx = blockIdx.x * 256 + threadIdx.x;
    if (idx >= 5 * 64 * 192) return;
    int l = idx / (64 * 192);
    int rem = idx % (64 * 192);
    int k = rem / 192, j = rem % 192;
    const float* a = ggc + (l * 64 + k) * 64;
    const float* w = w_ih + j * 64;
    float s = 0.f;
#pragma unroll 8
    for (int c = 0; c < 64; c++) s += a[c] * w[c];
    g_P[idx] = s;
}

__global__ void k_prep_T(const float* __restrict__ w_hh,
                         const float* __restrict__ ai_w,
                         const float* __restrict__ aj_w) {
    int idx = blockIdx.x * 256 + threadIdx.x;
    if (idx < 12288) {
        int k = idx / 192, j = idx % 192;
        g_WHH[idx] = w_hh[j * 64 + k];
    } else if (idx < 12288 + 16384) {
        int i = idx - 12288;
        int k = i / 128, j = i % 128;
        g_AIW[i] = ai_w[j * 128 + k];
    } else if (idx < 12288 + 32768) {
        int i = idx - 28672;
        int k = i / 128, j = i % 128;
        g_AJW[i] = aj_w[j * 128 + k];
    }
}

__global__ void k_init(const float* __restrict__ nodes) {
    int n = blockIdx.x;
    int t = threadIdx.x;          // 0..255 -> (b,c)
    int c = t & 63;
    float v = (c < 63) ? nodes[n * 63 + c] : 0.f;
    int idx = n * ROWF + t;
    g_X0[idx] = v;
    g_X[0][idx] = v;
}

__global__ void k_cov(const float* __restrict__ cov, const int* __restrict__ c2l) {
    int idx = blockIdx.x * 256 + threadIdx.x;
    if (idx >= BB * NLBL) return;
    int b = idx / NLBL, j = idx % NLBL;
    int lbl = c2l[j];
    float v = cov[idx];
    int pos = lbl * ROWF + b * 64 + 63;
    g_X0[pos] = v;
    g_X[0][pos] = v;
}

__global__ void k_zero_pool() {
    int idx = blockIdx.x * 256 + threadIdx.x;
    if (idx < 512) g_POOL[idx] = 0.f;
}

// ---------------- CSR build (once per launch) ----------------
__global__ void k_zero_cnt() {
    int i = blockIdx.x * 256 + threadIdx.x;
    if (i < NN) g_cnt[i] = 0;
}

__global__ void k_hist(const int* __restrict__ edges) {
    int e = blockIdx.x * 256 + threadIdx.x;
    if (e < EE) atomicAdd(&g_cnt[edges[EE + e]], 1);
}

// single block, 1024 threads: exclusive scan of g_cnt -> g_off, g_cur
__global__ void __launch_bounds__(1024, 1) k_scan() {
    __shared__ int sp[1024];
    const int CH = (NN + 1023) / 1024;   // 49
    int t = threadIdx.x;
    int b0 = t * CH;
    int s = 0;
    for (int i = 0; i < CH; i++) {
        int n = b0 + i;
        if (n < NN) s += g_cnt[n];
    }
    sp[t] = s;
    __syncthreads();
    for (int off = 1; off < 1024; off <<= 1) {
        int v = (t >= off) ? sp[t - off] : 0;
        __syncthreads();
        sp[t] += v;
        __syncthreads();
    }
    int base = sp[t] - s;     // exclusive prefix
    for (int i = 0; i < CH; i++) {
        int n = b0 + i;
        if (n < NN) {
            g_off[n] = base;
            g_cur[n] = base;
            base += g_cnt[n];
        }
    }
}

__global__ void k_fill(const int* __restrict__ edges) {
    int e = blockIdx.x * 256 + threadIdx.x;
    if (e >= EE) return;
    int dst = edges[EE + e];
    int pos = atomicAdd(&g_cur[dst], 1);
    g_csr[pos] = edges[e];
}

// ---------------- edge gather: AGG[dst] = sum_{src in CSR(dst)} X[src] ----------------
// 64 threads per dst node, each owns one float4 of the 1KB row. No atomics.
__global__ void __launch_bounds__(256, 8) k_gather(int sel) {
    unsigned gid = blockIdx.x * 256u + threadIdx.x;
    int node = gid >> 6;
    int q = (gid & 63) * 4;
    if (node >= NN) return;
    const float* __restrict__ X = g_X[sel];
    int beg = g_off[node];
    int cnt = g_cnt[node];
    float4 acc = make_float4(0.f, 0.f, 0.f, 0.f);
    int j = 0;
    for (; j + 4 <= cnt; j += 4) {
        int i0 = g_csr[beg + j];
        int i1 = g_csr[beg + j + 1];
        int i2 = g_csr[beg + j + 2];
        int i3 = g_csr[beg + j + 3];
        const float4 v0 = *(const float4*)(X + i0 * ROWF + q);
        const float4 v1 = *(const float4*)(X + i1 * ROWF + q);
        const float4 v2 = *(const float4*)(X + i2 * ROWF + q);
        const float4 v3 = *(const float4*)(X + i3 * ROWF + q);
        acc.x += v0.x + v1.x + v2.x + v3.x;
        acc.y += v0.y + v1.y + v2.y + v3.y;
        acc.z += v0.z + v1.z + v2.z + v3.z;
        acc.w += v0.w + v1.w + v2.w + v3.w;
    }
    for (; j < cnt; j++) {
        int i0 = g_csr[beg + j];
        const float4 v0 = *(const float4*)(X + i0 * ROWF + q);
        acc.x += v0.x; acc.y += v0.y; acc.z += v0.z; acc.w += v0.w;
    }
    *(float4*)(g_AGG + node * ROWF + q) = acc;
}

// ---------------- fused GGC+GRU layer: x_new = GRU(AGG @ P, x) ----------------
// tile: 32 rows x 192 cols, two GEMMs (gx from AGG, gh from x) fused, K=64.
// 256 threads: warp w owns local rows [w*4, w*4+4); lane owns cols lane*2+{0,1}+64t, t<3.
// inner loop in packed f32x2 (FFMA2): lane's col pair = one 64-bit accumulator.
#define GRU_TILES 8
__global__ void __launch_bounds__(256, 1)
k_gru(const float* __restrict__ b_ih, const float* __restrict__ b_hh, int layer, int sel) {
    extern __shared__ float sm[];
    float* sP = sm;               // 64*192
    float* sW = sm + 12288;       // 64*192
    float* sA = sm + 24576;       // [64][36] aggT
    float* sX = sA + 64 * 36;     // [64][36] xT

    const float* P  = g_P + layer * 12288;
    const float* Xc = g_X[sel];
    float*       Xn = g_X[sel ^ 1];

    int tid = threadIdx.x, lane = tid & 31, warp = tid >> 5;

    for (int i = tid; i < 3072; i += 256) {
        ((float4*)sP)[i] = ((const float4*)P)[i];
        ((float4*)sW)[i] = ((const float4*)g_WHH)[i];
    }
    float bi[3][2], bh[3][2];
#pragma unroll
    for (int t = 0; t < 3; t++) {
        bi[t][0] = b_ih[64 * t + lane * 2];
        bi[t][1] = b_ih[64 * t + lane * 2 + 1];
        bh[t][0] = b_hh[64 * t + lane * 2];
        bh[t][1] = b_hh[64 * t + lane * 2 + 1];
    }
    __syncthreads();

    for (int it = 0; it < GRU_TILES; it++) {
        int tile = blockIdx.x * GRU_TILES + it;
        bool valid = tile < NTILES;
        int row0 = tile * 32;
        if (valid) {
#pragma unroll
            for (int iter = 0; iter < 2; iter++) {
                int k4 = warp + iter * 8;   // float4 chunk of k
                const float4 va = *(const float4*)(g_AGG + (row0 + lane) * CC + k4 * 4);
                const float4 vx = *(const float4*)(Xc    + (row0 + lane) * CC + k4 * 4);
                sA[(k4 * 4 + 0) * 36 + lane] = va.x;
                sA[(k4 * 4 + 1) * 36 + lane] = va.y;
                sA[(k4 * 4 + 2) * 36 + lane] = va.z;
                sA[(k4 * 4 + 3) * 36 + lane] = va.w;
                sX[(k4 * 4 + 0) * 36 + lane] = vx.x;
                sX[(k4 * 4 + 1) * 36 + lane] = vx.y;
                sX[(k4 * 4 + 2) * 36 + lane] = vx.z;
                sX[(k4 * 4 + 3) * 36 + lane] = vx.w;
            }
        }
        __syncthreads();
        if (valid) {
            unsigned long long axp[4][3], ahp[4][3];
#pragma unroll
            for (int nd = 0; nd < 4; nd++)
#pragma unroll
                for (int t = 0; t < 3; t++) { axp[nd][t] = 0ull; ahp[nd][t] = 0ull; }

#pragma unroll 2
            for (int k = 0; k < 64; k++) {
                float4 a4 = *(const float4*)&sA[k * 36 + warp * 4];
                float4 x4 = *(const float4*)&sX[k * 36 + warp * 4];
                unsigned long long pv[3], wv[3];
                pv[0] = *(const unsigned long long*)&sP[k * 192 +       lane * 2];
                pv[1] = *(const unsigned long long*)&sP[k * 192 +  64 + lane * 2];
                pv[2] = *(const unsigned long long*)&sP[k * 192 + 128 + lane * 2];
                wv[0] = *(const unsigned long long*)&sW[k * 192 +       lane * 2];
                wv[1] = *(const unsigned long long*)&sW[k * 192 +  64 + lane * 2];
                wv[2] = *(const unsigned long long*)&sW[k * 192 + 128 + lane * 2];
                float aa[4] = {a4.x, a4.y, a4.z, a4.w};
                float xx[4] = {x4.x, x4.y, x4.z, x4.w};
#pragma unroll
                for (int nd = 0; nd < 4; nd++) {
                    unsigned long long ab, xb;
                    PACK2BC(ab, aa[nd]);
                    PACK2BC(xb, xx[nd]);
#pragma unroll
                    for (int t = 0; t < 3; t++) {
                        FMA2(axp[nd][t], ab, pv[t]);
                        FMA2(ahp[nd][t], xb, wv[t]);
                    }
                }
            }
#pragma unroll
            for (int nd = 0; nd < 4; nd++) {
                int row = row0 + warp * 4 + nd;
                float2 h2 = *(const float2*)&Xc[row * CC + lane * 2];
                float hv[2] = {h2.x, h2.y};
                float axv[3][2], ahv[3][2];
#pragma unroll
                for (int t = 0; t < 3; t++) {
                    UNPACK2(axv[t][0], axv[t][1], axp[nd][t]);
                    UNPACK2(ahv[t][0], ahv[t][1], ahp[nd][t]);
                }
                float o[2];
#pragma unroll
                for (int c2 = 0; c2 < 2; c2++) {
                    float r  = sigm(axv[0][c2] + bi[0][c2] + ahv[0][c2] + bh[0][c2]);
                    float z  = sigm(axv[1][c2] + bi[1][c2] + ahv[1][c2] + bh[1][c2]);
                    float nn = tanhf(axv[2][c2] + bi[2][c2] + r * (ahv[2][c2] + bh[2][c2]));
                    o[c2] = (1.f - z) * nn + z * hv[c2];
                }
                *(float2*)&Xn[row * CC + lane * 2] = make_float2(o[0], o[1]);
            }
        }
        __syncthreads();
    }
}

// ---------------- attention + pooling ----------------
// cat = [x, x0] (K=128); a_i = sigmoid(cat@ai_w^T+b), a_j = relu(cat@aj_w^T+b)
// POOL[b][j] += a_i*a_j summed over nodes. rows are (n*4+b) so b == local row % 4.
__global__ void __launch_bounds__(256, 1)
k_att(const float* __restrict__ ai_b, const float* __restrict__ aj_b, int sel) {
    extern __shared__ float sm[];
    float* sAI = sm;              // 128*128
    float* sAJ = sm + 16384;      // 128*128
    float* sC  = sm + 32768;      // [128][36] catT, reused for reduction (4096 < 4608)

    const float* Xf = g_X[sel];
    int tid = threadIdx.x, lane = tid & 31, warp = tid >> 5;

    for (int i = tid; i < 4096; i += 256) {
        ((float4*)sAI)[i] = ((const float4*)g_AIW)[i];
        ((float4*)sAJ)[i] = ((const float4*)g_AJW)[i];
    }
    float aib[2][2], ajb[2][2];
#pragma unroll
    for (int t = 0; t < 2; t++) {
        aib[t][0] = ai_b[64 * t + lane * 2];
        aib[t][1] = ai_b[64 * t + lane * 2 + 1];
        ajb[t][0] = aj_b[64 * t + lane * 2];
        ajb[t][1] = aj_b[64 * t + lane * 2 + 1];
    }
    float asum[4][2][2] = {};    // [b][t][c2]
    __syncthreads();

    for (int it = 0; it < 8; it++) {
        int tile = blockIdx.x * 8 + it;
        bool valid = tile < NTILES;
        int row0 = tile * 32;
        if (valid) {
#pragma unroll
            for (int iter = 0; iter < 4; iter++) {
                int k0 = (warp + iter * 8) * 4;     // 0..124
                float4 v = (k0 < 64)
                    ? *(const float4*)(Xf   + (row0 + lane) * CC + k0)
                    : *(const float4*)(g_X0 + (row0 + lane) * CC + k0 - 64);
                sC[(k0 + 0) * 36 + lane] = v.x;
                sC[(k0 + 1) * 36 + lane] = v.y;
                sC[(k0 + 2) * 36 + lane] = v.z;
                sC[(k0 + 3) * 36 + lane] = v.w;
            }
        }
        __syncthreads();
        if (valid) {
            unsigned long long aip[4][2], ajp[4][2];
#pragma unroll
            for (int nd = 0; nd < 4; nd++)
#pragma unroll
                for (int t = 0; t < 2; t++) { aip[nd][t] = 0ull; ajp[nd][t] = 0ull; }

#pragma unroll 2
            for (int k = 0; k < 128; k++) {
                float4 c4 = *(const float4*)&sC[k * 36 + warp * 4];
                unsigned long long iv[2], jv[2];
                iv[0] = *(const unsigned long long*)&sAI[k * 128 +      lane * 2];
                iv[1] = *(const unsigned long long*)&sAI[k * 128 + 64 + lane * 2];
                jv[0] = *(const unsigned long long*)&sAJ[k * 128 +      lane * 2];
                jv[1] = *(const unsigned long long*)&sAJ[k * 128 + 64 + lane * 2];
                float cc[4] = {c4.x, c4.y, c4.z, c4.w};
#pragma unroll
                for (int nd = 0; nd < 4; nd++) {
                    unsigned long long cb;
                    PACK2BC(cb, cc[nd]);
#pragma unroll
                    for (int t = 0; t < 2; t++) {
                        FMA2(aip[nd][t], cb, iv[t]);
                        FMA2(ajp[nd][t], cb, jv[t]);
                    }
                }
            }
#pragma unroll
            for (int nd = 0; nd < 4; nd++)
#pragma unroll
                for (int t = 0; t < 2; t++) {
                    float av[2], jv2[2];
                    UNPACK2(av[0], av[1], aip[nd][t]);
                    UNPACK2(jv2[0], jv2[1], ajp[nd][t]);
#pragma unroll
                    for (int c2 = 0; c2 < 2; c2++) {
                        float a = sigm(av[c2] + aib[t][c2]);
                        float r = jv2[c2] + ajb[t][c2];
                        r = r > 0.f ? r : 0.f;
                        asum[nd][t][c2] += a * r;   // nd == batch index
                    }
                }
        }
        __syncthreads();
    }

    // cross-warp reduce into POOL
#pragma unroll
    for (int nd = 0; nd < 4; nd++)
#pragma unroll
        for (int t = 0; t < 2; t++)
#pragma unroll
            for (int c2 = 0; c2 < 2; c2++)
                sC[(warp * 4 + nd) * 128 + (t * 64 + lane * 2 + c2)] = asum[nd][t][c2];
    __syncthreads();
    for (int i = tid; i < 512; i += 256) {
        int b = i >> 7, j = i & 127;
        float s = 0.f;
#pragma unroll
        for (int w = 0; w < 8; w++) s += sC[(w * 4 + b) * 128 + j];
        atomicAdd(&g_POOL[b * 128 + j], s);
    }
}

// ---------------- final head ----------------
__global__ void k_head(const float* __restrict__ mlp_w, const float* __restrict__ mlp_b,
                       const float* __restrict__ cw, const float* __restrict__ cb,
                       float* __restrict__ out) {
    __shared__ float pooled[512];
    __shared__ float st[1024];
    int tid = threadIdx.x;
    for (int i = tid; i < 512; i += 256) pooled[i] = fmaxf(g_POOL[i], 0.f);
    __syncthreads();
    float acc[4] = {0.f, 0.f, 0.f, 0.f};
    for (int k = 0; k < 128; k++) {
        float w = mlp_w[tid * 128 + k];
#pragma unroll
        for (int b = 0; b < 4; b++) acc[b] += pooled[b * 128 + k] * w;
    }
    float mb = mlp_b[tid];
#pragma unroll
    for (int b = 0; b < 4; b++) st[b * 256 + tid] = fmaxf(acc[b] + mb, 0.f);
    __syncthreads();
    if (tid < 128) {
        int w = tid >> 5, lane = tid & 31;
        float s = 0.f;
        for (int k = lane; k < 256; k += 32) s += st[w * 256 + k] * cw[k];
#pragma unroll
        for (int off = 16; off; off >>= 1) s += __shfl_xor_sync(0xffffffffu, s, off);
        if (lane == 0) out[w] = s + cb[0];
    }
}

// ---------------- launch ----------------
extern "C" void kernel_launch(void* const* d_in, const int* in_sizes, int n_in,
                              void* d_out, int out_size) {
    const float* cov    = (const float*)d_in[0];
    const float* nodes  = (const float*)d_in[1];
    const int*   edges  = (const int*)  d_in[2];
    const int*   c2l    = (const int*)  d_in[3];
    const float* ggc    = (const float*)d_in[4];
    const float* w_ih   = (const float*)d_in[5];
    const float* w_hh   = (const float*)d_in[6];
    const float* b_ih   = (const float*)d_in[7];
    const float* b_hh   = (const float*)d_in[8];
    const float* ai_w   = (const float*)d_in[9];
    const float* ai_b   = (const float*)d_in[10];
    const float* aj_w   = (const float*)d_in[11];
    const float* aj_b   = (const float*)d_in[12];
    const float* mlp_w  = (const float*)d_in[13];
    const float* mlp_b  = (const float*)d_in[14];
    const float* cw     = (const float*)d_in[15];
    const float* cb     = (const float*)d_in[16];
    float* out = (float*)d_out;

    const int smem_gru = 29184 * 4;     // 116736 B
    const int smem_att = 37376 * 4;     // 149504 B
    cudaFuncSetAttribute(k_gru, cudaFuncAttributeMaxDynamicSharedMemorySize, smem_gru);
    cudaFuncSetAttribute(k_att, cudaFuncAttributeMaxDynamicSharedMemorySize, smem_att);

    // prep + CSR build (independent of layer loop)
    k_prep_P<<<240, 256>>>(ggc, w_ih);
    k_prep_T<<<176, 256>>>(w_hh, ai_w, aj_w);
    k_init<<<NN, 256>>>(nodes);
    k_cov<<<(BB * NLBL + 255) / 256, 256>>>(cov, c2l);

    k_zero_cnt<<<(NN + 255) / 256, 256>>>();
    k_hist<<<(EE + 255) / 256, 256>>>(edges);
    k_scan<<<1, 1024>>>();
    k_fill<<<(EE + 255) / 256, 256>>>(edges);

    int sel = 0;
    for (int l = 0; l < 5; l++) {
        k_gather<<<(NN * 64 + 255) / 256, 256>>>(sel);
        k_gru<<<(NTILES + GRU_TILES - 1) / GRU_TILES, 256, smem_gru>>>(b_ih, b_hh, l, sel);
        sel ^= 1;
    }

    k_zero_pool<<<2, 256>>>();
    k_att<<<(NTILES + 7) / 8, 256, smem_att>>>(ai_b, aj_b, sel);
    k_head<<<1, 256>>>(mlp_w, mlp_b, cw, cb, out);
}

// round 11
// speedup vs baseline: 1.3617x; 1.3617x over previous
#include <cuda_runtime.h>
#include <math.h>

#define BB   4
#define NN   50000
#define CC   64
#define EE   800000
#define NLBL 10000
#define RR   (NN*BB)        /* 200000 GEMM rows (node,batch) */
#define ROWF (BB*CC)        /* 256 floats per node across batches */
#define NT64 (RR/64)        /* 3125 64-row tiles */

// ---------------- device scratch (no allocations allowed) ----------------
__device__ float g_X[2][RR*CC];     // ping-pong node state, 2 x 51.2MB
__device__ float g_X0[RR*CC];       // initial features (needed for attention)
__device__ float g_AGG[RR*CC];      // neighbor sums
__device__ float g_P[5*64*192];     // P[l] = ggc[l] @ w_ih^T, [k][j] layout
__device__ float g_WHH[64*192];     // w_hh^T, [k][j]
__device__ float g_AIW[128*128];    // ai_w^T, [k][j]
__device__ float g_AJW[128*128];    // aj_w^T, [k][j]
__device__ float g_POOL[512];       // att pooled sums [b][128]
// CSR by destination
__device__ int   g_cnt[NN];
__device__ int   g_off[NN];
__device__ int   g_cur[NN];
__device__ int   g_csr[EE];

__device__ __forceinline__ float sigm(float v) { return 1.0f / (1.0f + expf(-v)); }

// ---------------- prep kernels ----------------
__global__ void k_prep_P(const float* __restrict__ ggc, const float* __restrict__ w_ih) {
    int idx = blockIdx.x * 256 + threadIdx.x;
    if (idx >= 5 * 64 * 192) return;
    int l = idx / (64 * 192);
    int rem = idx % (64 * 192);
    int k = rem / 192, j = rem % 192;
    const float* a = ggc + (l * 64 + k) * 64;
    const float* w = w_ih + j * 64;
    float s = 0.f;
#pragma unroll 8
    for (int c = 0; c < 64; c++) s += a[c] * w[c];
    g_P[idx] = s;
}

__global__ void k_prep_T(const float* __restrict__ w_hh,
                         const float* __restrict__ ai_w,
                         const float* __restrict__ aj_w) {
    int idx = blockIdx.x * 256 + threadIdx.x;
    if (idx < 12288) {
        int k = idx / 192, j = idx % 192;
        g_WHH[idx] = w_hh[j * 64 + k];
    } else if (idx < 12288 + 16384) {
        int i = idx - 12288;
        int k = i / 128, j = i % 128;
        g_AIW[i] = ai_w[j * 128 + k];
    } else if (idx < 12288 + 32768) {
        int i = idx - 28672;
        int k = i / 128, j = i % 128;
        g_AJW[i] = aj_w[j * 128 + k];
    }
}

__global__ void k_init(const float* __restrict__ nodes) {
    int n = blockIdx.x;
    int t = threadIdx.x;          // 0..255 -> (b,c)
    int c = t & 63;
    float v = (c < 63) ? nodes[n * 63 + c] : 0.f;
    int idx = n * ROWF + t;
    g_X0[idx] = v;
    g_X[0][idx] = v;
}

__global__ void k_cov(const float* __restrict__ cov, const int* __restrict__ c2l) {
    int idx = blockIdx.x * 256 + threadIdx.x;
    if (idx >= BB * NLBL) return;
    int b = idx / NLBL, j = idx % NLBL;
    int lbl = c2l[j];
    float v = cov[idx];
    int pos = lbl * ROWF + b * 64 + 63;
    g_X0[pos] = v;
    g_X[0][pos] = v;
}

__global__ void k_zero_pool() {
    int idx = blockIdx.x * 256 + threadIdx.x;
    if (idx < 512) g_POOL[idx] = 0.f;
}

// ---------------- CSR build (once per launch) ----------------
__global__ void k_zero_cnt() {
    int i = blockIdx.x * 256 + threadIdx.x;
    if (i < NN) g_cnt[i] = 0;
}

__global__ void k_hist(const int* __restrict__ edges) {
    int e = blockIdx.x * 256 + threadIdx.x;
    if (e < EE) atomicAdd(&g_cnt[edges[EE + e]], 1);
}

// single block, 1024 threads: exclusive scan of g_cnt -> g_off, g_cur
__global__ void __launch_bounds__(1024, 1) k_scan() {
    __shared__ int sp[1024];
    const int CH = (NN + 1023) / 1024;   // 49
    int t = threadIdx.x;
    int b0 = t * CH;
    int s = 0;
    for (int i = 0; i < CH; i++) {
        int n = b0 + i;
        if (n < NN) s += g_cnt[n];
    }
    sp[t] = s;
    __syncthreads();
    for (int off = 1; off < 1024; off <<= 1) {
        int v = (t >= off) ? sp[t - off] : 0;
        __syncthreads();
        sp[t] += v;
        __syncthreads();
    }
    int base = sp[t] - s;     // exclusive prefix
    for (int i = 0; i < CH; i++) {
        int n = b0 + i;
        if (n < NN) {
            g_off[n] = base;
            g_cur[n] = base;
            base += g_cnt[n];
        }
    }
}

__global__ void k_fill(const int* __restrict__ edges) {
    int e = blockIdx.x * 256 + threadIdx.x;
    if (e >= EE) return;
    int dst = edges[EE + e];
    int pos = atomicAdd(&g_cur[dst], 1);
    g_csr[pos] = edges[e];
}

// ---------------- edge gather: AGG[dst] = sum_{src in CSR(dst)} X[src] ----------------
// 64 threads per dst node, each owns one float4 of the 1KB row. No atomics.
__global__ void __launch_bounds__(256, 8) k_gather(int sel) {
    unsigned gid = blockIdx.x * 256u + threadIdx.x;
    int node = gid >> 6;
    int q = (gid & 63) * 4;
    if (node >= NN) return;
    const float* __restrict__ X = g_X[sel];
    int beg = g_off[node];
    int cnt = g_cnt[node];
    float4 acc = make_float4(0.f, 0.f, 0.f, 0.f);
    int j = 0;
    for (; j + 4 <= cnt; j += 4) {
        int i0 = g_csr[beg + j];
        int i1 = g_csr[beg + j + 1];
        int i2 = g_csr[beg + j + 2];
        int i3 = g_csr[beg + j + 3];
        const float4 v0 = *(const float4*)(X + i0 * ROWF + q);
        const float4 v1 = *(const float4*)(X + i1 * ROWF + q);
        const float4 v2 = *(const float4*)(X + i2 * ROWF + q);
        const float4 v3 = *(const float4*)(X + i3 * ROWF + q);
        acc.x += v0.x + v1.x + v2.x + v3.x;
        acc.y += v0.y + v1.y + v2.y + v3.y;
        acc.z += v0.z + v1.z + v2.z + v3.z;
        acc.w += v0.w + v1.w + v2.w + v3.w;
    }
    for (; j < cnt; j++) {
        int i0 = g_csr[beg + j];
        const float4 v0 = *(const float4*)(X + i0 * ROWF + q);
        acc.x += v0.x; acc.y += v0.y; acc.z += v0.z; acc.w += v0.w;
    }
    *(float4*)(g_AGG + node * ROWF + q) = acc;
}

// ---------------- fused GGC+GRU layer: x_new = GRU(AGG @ P, x) ----------------
// 512 threads, 64-row tiles, register double-buffered loads.
// warp w owns rows [w*4, w*4+4); lane owns cols lane*2+{0,1}+64t, t<3.
#define GRU_TILES 21
#define SROW 68
__global__ void __launch_bounds__(512, 1)
k_gru(const float* __restrict__ b_ih, const float* __restrict__ b_hh, int layer, int sel) {
    extern __shared__ float sm[];
    float* sP = sm;               // 64*192 = 12288
    float* sW = sm + 12288;       // 12288
    float* sA = sm + 24576;       // [64][68] aggT = 4352
    float* sX = sA + 64 * SROW;   // 4352   (total 33280 f = 133120 B)

    const float* P  = g_P + layer * 12288;
    const float* Xc = g_X[sel];
    float*       Xn = g_X[sel ^ 1];

    int tid = threadIdx.x, lane = tid & 31, warp = tid >> 5;
    int half = warp >> 3, k8 = warp & 7;   // load-phase mapping

    for (int i = tid; i < 3072; i += 512) {
        ((float4*)sP)[i] = ((const float4*)P)[i];
        ((float4*)sW)[i] = ((const float4*)g_WHH)[i];
    }
    float bi[3][2], bh[3][2];
#pragma unroll
    for (int t = 0; t < 3; t++) {
        bi[t][0] = b_ih[64 * t + lane * 2];
        bi[t][1] = b_ih[64 * t + lane * 2 + 1];
        bh[t][0] = b_hh[64 * t + lane * 2];
        bh[t][1] = b_hh[64 * t + lane * 2 + 1];
    }

    // prefetch tile 0
    float4 pa[2], px[2];
    int tile0 = blockIdx.x * GRU_TILES;
    if (tile0 < NT64) {
#pragma unroll
        for (int iter = 0; iter < 2; iter++) {
            int k4 = k8 + iter * 8;
            int row = tile0 * 64 + half * 32 + lane;
            pa[iter] = *(const float4*)(g_AGG + row * CC + k4 * 4);
            px[iter] = *(const float4*)(Xc    + row * CC + k4 * 4);
        }
    }
    __syncthreads();   // weights ready
    if (tile0 < NT64) {
#pragma unroll
        for (int iter = 0; iter < 2; iter++) {
            int k4 = k8 + iter * 8;
            int r = half * 32 + lane;
            sA[(k4 * 4 + 0) * SROW + r] = pa[iter].x;
            sA[(k4 * 4 + 1) * SROW + r] = pa[iter].y;
            sA[(k4 * 4 + 2) * SROW + r] = pa[iter].z;
            sA[(k4 * 4 + 3) * SROW + r] = pa[iter].w;
            sX[(k4 * 4 + 0) * SROW + r] = px[iter].x;
            sX[(k4 * 4 + 1) * SROW + r] = px[iter].y;
            sX[(k4 * 4 + 2) * SROW + r] = px[iter].z;
            sX[(k4 * 4 + 3) * SROW + r] = px[iter].w;
        }
    }
    __syncthreads();

    for (int it = 0; it < GRU_TILES; it++) {
        int tile = blockIdx.x * GRU_TILES + it;
        bool valid  = tile < NT64;
        bool nvalid = (it + 1 < GRU_TILES) && (tile + 1 < NT64);
        // prefetch next tile while computing this one
        if (nvalid) {
#pragma unroll
            for (int iter = 0; iter < 2; iter++) {
                int k4 = k8 + iter * 8;
                int row = (tile + 1) * 64 + half * 32 + lane;
                pa[iter] = *(const float4*)(g_AGG + row * CC + k4 * 4);
                px[iter] = *(const float4*)(Xc    + row * CC + k4 * 4);
            }
        }
        if (valid) {
            int row0 = tile * 64;
            float ax[4][3][2] = {};
            float ah[4][3][2] = {};
#pragma unroll 2
            for (int k = 0; k < 64; k++) {
                float4 a4 = *(const float4*)&sA[k * SROW + warp * 4];
                float4 x4 = *(const float4*)&sX[k * SROW + warp * 4];
                float2 p0 = *(const float2*)&sP[k * 192 +       lane * 2];
                float2 p1 = *(const float2*)&sP[k * 192 +  64 + lane * 2];
                float2 p2 = *(const float2*)&sP[k * 192 + 128 + lane * 2];
                float2 w0 = *(const float2*)&sW[k * 192 +       lane * 2];
                float2 w1 = *(const float2*)&sW[k * 192 +  64 + lane * 2];
                float2 w2 = *(const float2*)&sW[k * 192 + 128 + lane * 2];
                float aa[4] = {a4.x, a4.y, a4.z, a4.w};
                float xx[4] = {x4.x, x4.y, x4.z, x4.w};
                float pv[3][2] = {{p0.x, p0.y}, {p1.x, p1.y}, {p2.x, p2.y}};
                float wv[3][2] = {{w0.x, w0.y}, {w1.x, w1.y}, {w2.x, w2.y}};
#pragma unroll
                for (int nd = 0; nd < 4; nd++)
#pragma unroll
                    for (int t = 0; t < 3; t++)
#pragma unroll
                        for (int c2 = 0; c2 < 2; c2++) {
                            ax[nd][t][c2] += aa[nd] * pv[t][c2];
                            ah[nd][t][c2] += xx[nd] * wv[t][c2];
                        }
            }
#pragma unroll
            for (int nd = 0; nd < 4; nd++) {
                int row = row0 + warp * 4 + nd;
                float2 h2 = *(const float2*)&Xc[row * CC + lane * 2];
                float hv[2] = {h2.x, h2.y};
                float o[2];
#pragma unroll
                for (int c2 = 0; c2 < 2; c2++) {
                    float r  = sigm(ax[nd][0][c2] + bi[0][c2] + ah[nd][0][c2] + bh[0][c2]);
                    float z  = sigm(ax[nd][1][c2] + bi[1][c2] + ah[nd][1][c2] + bh[1][c2]);
                    float nn = tanhf(ax[nd][2][c2] + bi[2][c2] + r * (ah[nd][2][c2] + bh[2][c2]));
                    o[c2] = (1.f - z) * nn + z * hv[c2];
                }
                *(float2*)&Xn[row * CC + lane * 2] = make_float2(o[0], o[1]);
            }
        }
        __syncthreads();
        if (nvalid) {
#pragma unroll
            for (int iter = 0; iter < 2; iter++) {
                int k4 = k8 + iter * 8;
                int r = half * 32 + lane;
                sA[(k4 * 4 + 0) * SROW + r] = pa[iter].x;
                sA[(k4 * 4 + 1) * SROW + r] = pa[iter].y;
                sA[(k4 * 4 + 2) * SROW + r] = pa[iter].z;
                sA[(k4 * 4 + 3) * SROW + r] = pa[iter].w;
                sX[(k4 * 4 + 0) * SROW + r] = px[iter].x;
                sX[(k4 * 4 + 1) * SROW + r] = px[iter].y;
                sX[(k4 * 4 + 2) * SROW + r] = px[iter].z;
                sX[(k4 * 4 + 3) * SROW + r] = px[iter].w;
            }
        }
        __syncthreads();
    }
}

// ---------------- attention + pooling ----------------
// 512 threads, 64-row tiles, register double-buffered loads.
// cat = [x, x0] (K=128); POOL[b][j] += sigmoid(cat@ai^T+b)*relu(cat@aj^T+b).
#define ATT_TILES 21
__global__ void __launch_bounds__(512, 1)
k_att(const float* __restrict__ ai_b, const float* __restrict__ aj_b, int sel) {
    extern __shared__ float sm[];
    float* sAI = sm;              // 128*128 = 16384
    float* sAJ = sm + 16384;      // 16384
    float* sC  = sm + 32768;      // [128][68] = 8704, reused for reduction

    const float* Xf = g_X[sel];
    int tid = threadIdx.x, lane = tid & 31, warp = tid >> 5;
    int half = warp >> 3, k8 = warp & 7;

    for (int i = tid; i < 4096; i += 512) {     // 4096 float4 per 16384-float array
        ((float4*)sAI)[i] = ((const float4*)g_AIW)[i];
        ((float4*)sAJ)[i] = ((const float4*)g_AJW)[i];
    }
    float aib[2][2], ajb[2][2];
#pragma unroll
    for (int t = 0; t < 2; t++) {
        aib[t][0] = ai_b[64 * t + lane * 2];
        aib[t][1] = ai_b[64 * t + lane * 2 + 1];
        ajb[t][0] = aj_b[64 * t + lane * 2];
        ajb[t][1] = aj_b[64 * t + lane * 2 + 1];
    }
    float asum[4][2][2] = {};    // [b][t][c2]

    // prefetch tile 0: k4 = k8 + iter*8, iter<4 (covers K=128 float4 chunks 0..31)
    float4 pc[4];
    int tile0 = blockIdx.x * ATT_TILES;
    if (tile0 < NT64) {
#pragma unroll
        for (int iter = 0; iter < 4; iter++) {
            int k4 = k8 + iter * 8;
            int k0 = k4 * 4;
            int row = tile0 * 64 + half * 32 + lane;
            pc[iter] = (k0 < 64)
                ? *(const float4*)(Xf   + row * CC + k0)
                : *(const float4*)(g_X0 + row * CC + k0 - 64);
        }
    }
    __syncthreads();
    if (tile0 < NT64) {
#pragma unroll
        for (int iter = 0; iter < 4; iter++) {
            int k0 = (k8 + iter * 8) * 4;
            int r = half * 32 + lane;
            sC[(k0 + 0) * SROW + r] = pc[iter].x;
            sC[(k0 + 1) * SROW + r] = pc[iter].y;
            sC[(k0 + 2) * SROW + r] = pc[iter].z;
            sC[(k0 + 3) * SROW + r] = pc[iter].w;
        }
    }
    __syncthreads();

    for (int it = 0; it < ATT_TILES; it++) {
        int tile = blockIdx.x * ATT_TILES + it;
        bool valid  = tile < NT64;
        bool nvalid = (it + 1 < ATT_TILES) && (tile + 1 < NT64);
        if (nvalid) {
#pragma unroll
            for (int iter = 0; iter < 4; iter++) {
                int k4 = k8 + iter * 8;
                int k0 = k4 * 4;
                int row = (tile + 1) * 64 + half * 32 + lane;
                pc[iter] = (k0 < 64)
                    ? *(const float4*)(Xf   + row * CC + k0)
                    : *(const float4*)(g_X0 + row * CC + k0 - 64);
            }
        }
        if (valid) {
            float ai[4][2][2] = {};
            float aj[4][2][2] = {};
#pragma unroll 2
            for (int k = 0; k < 128; k++) {
                float4 c4 = *(const float4*)&sC[k * SROW + warp * 4];
                float2 i0 = *(const float2*)&sAI[k * 128 +      lane * 2];
                float2 i1 = *(const float2*)&sAI[k * 128 + 64 + lane * 2];
                float2 j0 = *(const float2*)&sAJ[k * 128 +      lane * 2];
                float2 j1 = *(const float2*)&sAJ[k * 128 + 64 + lane * 2];
                float cc[4] = {c4.x, c4.y, c4.z, c4.w};
                float iv[2][2] = {{i0.x, i0.y}, {i1.x, i1.y}};
                float jv[2][2] = {{j0.x, j0.y}, {j1.x, j1.y}};
#pragma unroll
                for (int nd = 0; nd < 4; nd++)
#pragma unroll
                    for (int t = 0; t < 2; t++)
#pragma unroll
                        for (int c2 = 0; c2 < 2; c2++) {
                            ai[nd][t][c2] += cc[nd] * iv[t][c2];
                            aj[nd][t][c2] += cc[nd] * jv[t][c2];
                        }
            }
#pragma unroll
            for (int nd = 0; nd < 4; nd++)
#pragma unroll
                for (int t = 0; t < 2; t++)
#pragma unroll
                    for (int c2 = 0; c2 < 2; c2++) {
                        float a = sigm(ai[nd][t][c2] + aib[t][c2]);
                        float r = aj[nd][t][c2] + ajb[t][c2];
                        r = r > 0.f ? r : 0.f;
                        asum[nd][t][c2] += a * r;   // nd == batch index
                    }
        }
        __syncthreads();
        if (nvalid) {
#pragma unroll
            for (int iter = 0; iter < 4; iter++) {
                int k0 = (k8 + iter * 8) * 4;
                int r = half * 32 + lane;
                sC[(k0 + 0) * SROW + r] = pc[iter].x;
                sC[(k0 + 1) * SROW + r] = pc[iter].y;
                sC[(k0 + 2) * SROW + r] = pc[iter].z;
                sC[(k0 + 3) * SROW + r] = pc[iter].w;
            }
        }
        __syncthreads();
    }

    // cross-warp reduce into POOL (16 warps x 4 nd rows x 128 cols <= 8704)
#pragma unroll
    for (int nd = 0; nd < 4; nd++)
#pragma unroll
        for (int t = 0; t < 2; t++)
#pragma unroll
            for (int c2 = 0; c2 < 2; c2++)
                sC[(warp * 4 + nd) * 128 + (t * 64 + lane * 2 + c2)] = asum[nd][t][c2];
    __syncthreads();
    {
        int i = tid;                   // 512 threads, 512 outputs
        int b = i >> 7, j = i & 127;
        float s = 0.f;
#pragma unroll
        for (int w = 0; w < 16; w++) s += sC[(w * 4 + b) * 128 + j];
        atomicAdd(&g_POOL[b * 128 + j], s);
    }
}

// ---------------- final head ----------------
__global__ void k_head(const float* __restrict__ mlp_w, const float* __restrict__ mlp_b,
                       const float* __restrict__ cw, const float* __restrict__ cb,
                       float* __restrict__ out) {
    __shared__ float pooled[512];
    __shared__ float st[1024];
    int tid = threadIdx.x;
    for (int i = tid; i < 512; i += 256) pooled[i] = fmaxf(g_POOL[i], 0.f);
    __syncthreads();
    float acc[4] = {0.f, 0.f, 0.f, 0.f};
    for (int k = 0; k < 128; k++) {
        float w = mlp_w[tid * 128 + k];
#pragma unroll
        for (int b = 0; b < 4; b++) acc[b] += pooled[b * 128 + k] * w;
    }
    float mb = mlp_b[tid];
#pragma unroll
    for (int b = 0; b < 4; b++) st[b * 256 + tid] = fmaxf(acc[b] + mb, 0.f);
    __syncthreads();
    if (tid < 128) {
        int w = tid >> 5, lane = tid & 31;
        float s = 0.f;
        for (int k = lane; k < 256; k += 32) s += st[w * 256 + k] * cw[k];
#pragma unroll
        for (int off = 16; off; off >>= 1) s += __shfl_xor_sync(0xffffffffu, s, off);
        if (lane == 0) out[w] = s + cb[0];
    }
}

// ---------------- launch ----------------
extern "C" void kernel_launch(void* const* d_in, const int* in_sizes, int n_in,
                              void* d_out, int out_size) {
    const float* cov    = (const float*)d_in[0];
    const float* nodes  = (const float*)d_in[1];
    const int*   edges  = (const int*)  d_in[2];
    const int*   c2l    = (const int*)  d_in[3];
    const float* ggc    = (const float*)d_in[4];
    const float* w_ih   = (const float*)d_in[5];
    const float* w_hh   = (const float*)d_in[6];
    const float* b_ih   = (const float*)d_in[7];
    const float* b_hh   = (const float*)d_in[8];
    const float* ai_w   = (const float*)d_in[9];
    const float* ai_b   = (const float*)d_in[10];
    const float* aj_w   = (const float*)d_in[11];
    const float* aj_b   = (const float*)d_in[12];
    const float* mlp_w  = (const float*)d_in[13];
    const float* mlp_b  = (const float*)d_in[14];
    const float* cw     = (const float*)d_in[15];
    const float* cb     = (const float*)d_in[16];
    float* out = (float*)d_out;

    const int smem_gru = 33280 * 4;     // 133120 B
    const int smem_att = 41472 * 4;     // 165888 B
    cudaFuncSetAttribute(k_gru, cudaFuncAttributeMaxDynamicSharedMemorySize, smem_gru);
    cudaFuncSetAttribute(k_att, cudaFuncAttributeMaxDynamicSharedMemorySize, smem_att);

    // prep + CSR build (independent of layer loop)
    k_prep_P<<<240, 256>>>(ggc, w_ih);
    k_prep_T<<<176, 256>>>(w_hh, ai_w, aj_w);
    k_init<<<NN, 256>>>(nodes);
    k_cov<<<(BB * NLBL + 255) / 256, 256>>>(cov, c2l);

    k_zero_cnt<<<(NN + 255) / 256, 256>>>();
    k_hist<<<(EE + 255) / 256, 256>>>(edges);
    k_scan<<<1, 1024>>>();
    k_fill<<<(EE + 255) / 256, 256>>>(edges);

    const int grid_gemm = (NT64 + GRU_TILES - 1) / GRU_TILES;   // 149
    int sel = 0;
    for (int l = 0; l < 5; l++) {
        k_gather<<<(NN * 64 + 255) / 256, 256>>>(sel);
        k_gru<<<grid_gemm, 512, smem_gru>>>(b_ih, b_hh, l, sel);
        sel ^= 1;
    }

    k_zero_pool<<<2, 256>>>();
    k_att<<<(NT64 + ATT_TILES - 1) / ATT_TILES, 512, smem_att>>>(ai_b, aj_b, sel);
    k_head<<<1, 256>>>(mlp_w, mlp_b, cw, cb, out);
}

// round 16
// speedup vs baseline: 1.6764x; 1.2311x over previous
#include <cuda_runtime.h>
#include <cuda_bf16.h>
#include <cstdint>
#include <math.h>

#define BB   4
#define NN   50000
#define CC   64
#define EE   800000
#define NLBL 10000
#define RR   (NN*BB)        /* 200000 GEMM rows (node,batch) */
#define ROWF (BB*CC)        /* 256 floats per node across batches */
#define NT64 (RR/64)        /* 3125 64-row tiles */
#define PADR 200064

// ---------------- device scratch ----------------
__device__ float g_X[2][RR*CC];          // ping-pong node state fp32
__device__ float g_X0[RR*CC];            // initial features
__device__ float g_AIW[128*128];         // ai_w^T, [k][j]
__device__ float g_AJW[128*128];         // aj_w^T, [k][j]
__device__ float g_POOL[512];
// split-bf16 planes (hi/lo) for HMMA GEMMs
__device__ __nv_bfloat16 g_AGH[PADR*CC], g_AGL[PADR*CC];         // AGG
__device__ __nv_bfloat16 g_XPH[2][PADR*CC], g_XPL[2][PADR*CC];   // X ping-pong
__device__ __nv_bfloat16 g_P2H[5*192*64], g_P2L[5*192*64];       // P^T [l][j][k]
__device__ __nv_bfloat16 g_W2H[192*64],  g_W2L[192*64];          // w_hh [j][k]
// CSR by destination
__device__ int   g_cnt[NN];
__device__ int   g_off[NN];
__device__ int   g_cur[NN];
__device__ int   g_csr[EE];

__device__ __forceinline__ float sigm(float v) { return 1.0f / (1.0f + expf(-v)); }

__device__ __forceinline__ void split_bf(float v, __nv_bfloat16& h, __nv_bfloat16& l) {
    h = __float2bfloat16_rn(v);
    l = __float2bfloat16_rn(v - __bfloat162float(h));
}
__device__ __forceinline__ unsigned short bfb(__nv_bfloat16 v) { return __bfloat16_as_ushort(v); }

__device__ __forceinline__ uint32_t smem_u32(const void* p) {
    uint32_t a;
    asm("{ .reg .u64 t; cvta.to.shared.u64 t, %1; cvt.u32.u64 %0, t; }" : "=r"(a) : "l"(p));
    return a;
}

#define LDSM4(r0, r1, r2, r3, addr) \
    asm volatile("ldmatrix.sync.aligned.m8n8.x4.shared.b16 {%0,%1,%2,%3}, [%4];" \
        : "=r"(r0), "=r"(r1), "=r"(r2), "=r"(r3) : "r"(addr))

#define MMA16816(d, a0, a1, a2, a3, b0, b1) \
    asm volatile("mma.sync.aligned.m16n8k16.row.col.f32.bf16.bf16.f32 " \
        "{%0,%1,%2,%3}, {%4,%5,%6,%7}, {%8,%9}, {%0,%1,%2,%3};" \
        : "+f"((d)[0]), "+f"((d)[1]), "+f"((d)[2]), "+f"((d)[3]) \
        : "r"(a0), "r"(a1), "r"(a2), "r"(a3), "r"(b0), "r"(b1))

// ---------------- prep kernels ----------------
__global__ void k_prep_W2(const float* __restrict__ ggc, const float* __restrict__ w_ih,
                          const float* __restrict__ w_hh) {
    int idx = blockIdx.x * 256 + threadIdx.x;
    if (idx < 5 * 192 * 64) {
        int l = idx / 12288, rem = idx % 12288;
        int j = rem / 64, k = rem % 64;
        const float* a = ggc + (l * 64 + k) * 64;
        const float* w = w_ih + j * 64;
        float s = 0.f;
#pragma unroll 8
        for (int c = 0; c < 64; c++) s += a[c] * w[c];
        __nv_bfloat16 h, lo; split_bf(s, h, lo);
        g_P2H[idx] = h; g_P2L[idx] = lo;
    } else if (idx < 5 * 12288 + 12288) {
        int i = idx - 61440;
        __nv_bfloat16 h, lo; split_bf(w_hh[i], h, lo);
        g_W2H[i] = h; g_W2L[i] = lo;
    }
}

__global__ void k_prep_T(const float* __restrict__ ai_w, const float* __restrict__ aj_w) {
    int idx = blockIdx.x * 256 + threadIdx.x;
    if (idx < 16384) {
        int k = idx / 128, j = idx % 128;
        g_AIW[idx] = ai_w[j * 128 + k];
    } else if (idx < 32768) {
        int i = idx - 16384;
        int k = i / 128, j = i % 128;
        g_AJW[i] = aj_w[j * 128 + k];
    }
}

__global__ void k_init(const float* __restrict__ nodes) {
    int n = blockIdx.x;
    int t = threadIdx.x;
    int c = t & 63;
    float v = (c < 63) ? nodes[n * 63 + c] : 0.f;
    int idx = n * ROWF + t;
    g_X0[idx] = v;
    g_X[0][idx] = v;
    __nv_bfloat16 h, l; split_bf(v, h, l);
    g_XPH[0][idx] = h; g_XPL[0][idx] = l;
}

__global__ void k_cov(const float* __restrict__ cov, const int* __restrict__ c2l) {
    int idx = blockIdx.x * 256 + threadIdx.x;
    if (idx >= BB * NLBL) return;
    int b = idx / NLBL, j = idx % NLBL;
    int lbl = c2l[j];
    float v = cov[idx];
    int pos = lbl * ROWF + b * 64 + 63;
    g_X0[pos] = v;
    g_X[0][pos] = v;
    __nv_bfloat16 h, l; split_bf(v, h, l);
    g_XPH[0][pos] = h; g_XPL[0][pos] = l;
}

__global__ void k_zero_pool() {
    int idx = blockIdx.x * 256 + threadIdx.x;
    if (idx < 512) g_POOL[idx] = 0.f;
}

// ---------------- CSR build ----------------
__global__ void k_zero_cnt() {
    int i = blockIdx.x * 256 + threadIdx.x;
    if (i < NN) g_cnt[i] = 0;
}
__global__ void k_hist(const int* __restrict__ edges) {
    int e = blockIdx.x * 256 + threadIdx.x;
    if (e < EE) atomicAdd(&g_cnt[edges[EE + e]], 1);
}
__global__ void __launch_bounds__(1024, 1) k_scan() {
    __shared__ int sp[1024];
    const int CH = (NN + 1023) / 1024;
    int t = threadIdx.x;
    int b0 = t * CH;
    int s = 0;
    for (int i = 0; i < CH; i++) { int n = b0 + i; if (n < NN) s += g_cnt[n]; }
    sp[t] = s;
    __syncthreads();
    for (int off = 1; off < 1024; off <<= 1) {
        int v = (t >= off) ? sp[t - off] : 0;
        __syncthreads();
        sp[t] += v;
        __syncthreads();
    }
    int base = sp[t] - s;
    for (int i = 0; i < CH; i++) {
        int n = b0 + i;
        if (n < NN) { g_off[n] = base; g_cur[n] = base; base += g_cnt[n]; }
    }
}
__global__ void k_fill(const int* __restrict__ edges) {
    int e = blockIdx.x * 256 + threadIdx.x;
    if (e >= EE) return;
    int dst = edges[EE + e];
    int pos = atomicAdd(&g_cur[dst], 1);
    g_csr[pos] = edges[e];
}

// ---------------- gather: AGG planes (split bf16) = sum of X rows ----------------
__global__ void __launch_bounds__(256, 8) k_gather(int sel) {
    unsigned gid = blockIdx.x * 256u + threadIdx.x;
    int node = gid >> 6;
    int q = (gid & 63) * 4;
    if (node >= NN) return;
    const float* __restrict__ X = g_X[sel];
    int beg = g_off[node];
    int cnt = g_cnt[node];
    float4 acc = make_float4(0.f, 0.f, 0.f, 0.f);
    int j = 0;
    for (; j + 4 <= cnt; j += 4) {
        int i0 = g_csr[beg + j];
        int i1 = g_csr[beg + j + 1];
        int i2 = g_csr[beg + j + 2];
        int i3 = g_csr[beg + j + 3];
        const float4 v0 = *(const float4*)(X + i0 * ROWF + q);
        const float4 v1 = *(const float4*)(X + i1 * ROWF + q);
        const float4 v2 = *(const float4*)(X + i2 * ROWF + q);
        const float4 v3 = *(const float4*)(X + i3 * ROWF + q);
        acc.x += v0.x + v1.x + v2.x + v3.x;
        acc.y += v0.y + v1.y + v2.y + v3.y;
        acc.z += v0.z + v1.z + v2.z + v3.z;
        acc.w += v0.w + v1.w + v2.w + v3.w;
    }
    for (; j < cnt; j++) {
        int i0 = g_csr[beg + j];
        const float4 v0 = *(const float4*)(X + i0 * ROWF + q);
        acc.x += v0.x; acc.y += v0.y; acc.z += v0.z; acc.w += v0.w;
    }
    float vv[4] = {acc.x, acc.y, acc.z, acc.w};
    unsigned short hs[4], ls[4];
#pragma unroll
    for (int i = 0; i < 4; i++) {
        __nv_bfloat16 h, l; split_bf(vv[i], h, l);
        hs[i] = bfb(h); ls[i] = bfb(l);
    }
    size_t po = (size_t)node * ROWF + q;
    uint2 uh, ul;
    uh.x = (uint32_t)hs[0] | ((uint32_t)hs[1] << 16);
    uh.y = (uint32_t)hs[2] | ((uint32_t)hs[3] << 16);
    ul.x = (uint32_t)ls[0] | ((uint32_t)ls[1] << 16);
    ul.y = (uint32_t)ls[2] | ((uint32_t)ls[3] << 16);
    *(uint2*)((char*)g_AGH + po * 2) = uh;
    *(uint2*)((char*)g_AGL + po * 2) = ul;
}

// ---------------- HMMA (mma.sync bf16 split) GGC+GRU layer ----------------
// gx = AGG @ P^T, gh = X @ Whh^T; each via 3-term split-bf16 mma.
// Persistent 148 CTAs; 64-row tiles; 8 warps: warp = (rowgrp rg=w&3 -> 16 rows,
// colgrp cg=w>>2 -> 32 gate-cols of each of 3 gates, BOTH gemms). Accum 96 f32/thread.
// SMEM rows padded to 144B for conflict-free ldmatrix.
#define OFS_BIAS 0
#define OFS_AGH  1024
#define OFS_AGL  10240
#define OFS_XH   19456
#define OFS_XL   28672
#define OFS_PH   37888
#define OFS_PL   65536
#define OFS_WH   93184
#define OFS_WL   120832
#define SMEM_MMA 148480

__global__ void __launch_bounds__(256, 1)
k_gru_mma(const float* __restrict__ b_ih, const float* __restrict__ b_hh, int layer, int sel) {
    extern __shared__ char smem[];
    uint32_t sb = smem_u32(smem);
    int tid = threadIdx.x, lane = tid & 31, wid = tid >> 5;
    int rg = wid & 3, cg = wid >> 2;

    float* sB = (float*)(smem + OFS_BIAS);
    if (tid < 64) {
        sB[tid]       = b_ih[tid]       + b_hh[tid];        // r
        sB[64 + tid]  = b_ih[64 + tid]  + b_hh[64 + tid];   // z
        sB[128 + tid] = b_ih[128 + tid];                    // n (ih)
        sB[192 + tid] = b_hh[128 + tid];                    // n (hh)
    }
    // weights -> smem, [j][k] rows padded to 144B, 16B chunks
    {
        const uint4* s0 = (const uint4*)(g_P2H + layer * 12288);
        const uint4* s1 = (const uint4*)(g_P2L + layer * 12288);
        const uint4* s2 = (const uint4*)g_W2H;
        const uint4* s3 = (const uint4*)g_W2L;
        for (int i = tid; i < 1536; i += 256) {
            int row = i >> 3, ch = i & 7;
            int dst = row * 144 + ch * 16;
            *(uint4*)(smem + OFS_PH + dst) = s0[i];
            *(uint4*)(smem + OFS_PL + dst) = s1[i];
            *(uint4*)(smem + OFS_WH + dst) = s2[i];
            *(uint4*)(smem + OFS_WL + dst) = s3[i];
        }
    }
    __syncthreads();

    const float* Xc = g_X[sel];
    float*       Xn = g_X[sel ^ 1];
    const __nv_bfloat16* pXH = g_XPH[sel];
    const __nv_bfloat16* pXL = g_XPL[sel];
    __nv_bfloat16* nXH = g_XPH[sel ^ 1];
    __nv_bfloat16* nXL = g_XPL[sel ^ 1];

    // ldmatrix per-lane row offsets
    int lr = lane & 7, lsel = lane >> 3;
    // A (16x16): m0 rows0-7/k0-7, m1 rows8-15/k0-7, m2 rows0-7/k8-15, m3 rows8-15/k8-15
    uint32_t rowoff_a = (uint32_t)(lr + ((lsel & 1) ? 8 : 0)) * 144 + ((lsel >> 1) & 1) * 16;
    // B (two ntiles x k16): m0 n0-7/k0-7, m1 n0-7/k8-15, m2 n8-15/k0-7, m3 n8-15/k8-15
    uint32_t rowoff_b = (uint32_t)(lr + ((lsel >= 2) ? 8 : 0)) * 144 + (lsel & 1) * 16;

    uint32_t aBase[2][2] = {{sb + OFS_AGH, sb + OFS_AGL}, {sb + OFS_XH, sb + OFS_XL}};
    uint32_t wBase[2][2] = {{sb + OFS_PH,  sb + OFS_PL},  {sb + OFS_WH, sb + OFS_WL}};

    for (int t = blockIdx.x; t < NT64; t += 148) {
        // stage A planes: 64 rows x 64 k halves, pad rows to 144B
        {
            const uint4* s0 = (const uint4*)(g_AGH + (size_t)t * 4096);
            const uint4* s1 = (const uint4*)(g_AGL + (size_t)t * 4096);
            const uint4* s2 = (const uint4*)(pXH + (size_t)t * 4096);
            const uint4* s3 = (const uint4*)(pXL + (size_t)t * 4096);
            for (int i = tid; i < 512; i += 256) {
                int row = i >> 3, ch = i & 7;
                int dst = row * 144 + ch * 16;
                *(uint4*)(smem + OFS_AGH + dst) = s0[i];
                *(uint4*)(smem + OFS_AGL + dst) = s1[i];
                *(uint4*)(smem + OFS_XH + dst) = s2[i];
                *(uint4*)(smem + OFS_XL + dst) = s3[i];
            }
        }
        __syncthreads();

        float d[2][3][4][4];
#pragma unroll
        for (int g = 0; g < 2; g++)
#pragma unroll
            for (int ga = 0; ga < 3; ga++)
#pragma unroll
                for (int nt = 0; nt < 4; nt++)
#pragma unroll
                    for (int e = 0; e < 4; e++) d[g][ga][nt][e] = 0.f;

        uint32_t R0b = (uint32_t)(rg * 16) * 144;
#pragma unroll
        for (int ks = 0; ks < 4; ks++) {
            uint32_t kb = ks * 32;   // 16 halves = 32 bytes
#pragma unroll
            for (int g = 0; g < 2; g++) {
                uint32_t ah0, ah1, ah2, ah3, al0, al1, al2, al3;
                LDSM4(ah0, ah1, ah2, ah3, aBase[g][0] + R0b + kb + rowoff_a);
                LDSM4(al0, al1, al2, al3, aBase[g][1] + R0b + kb + rowoff_a);
#pragma unroll
                for (int ga = 0; ga < 3; ga++) {
#pragma unroll
                    for (int np = 0; np < 2; np++) {
                        uint32_t J0b = (uint32_t)(ga * 64 + cg * 32 + np * 16) * 144;
                        uint32_t bh0, bh1, bh2, bh3, bl0, bl1, bl2, bl3;
                        LDSM4(bh0, bh1, bh2, bh3, wBase[g][0] + J0b + kb + rowoff_b);
                        LDSM4(bl0, bl1, bl2, bl3, wBase[g][1] + J0b + kb + rowoff_b);
                        MMA16816(d[g][ga][np * 2],     ah0, ah1, ah2, ah3, bh0, bh1);
                        MMA16816(d[g][ga][np * 2],     ah0, ah1, ah2, ah3, bl0, bl1);
                        MMA16816(d[g][ga][np * 2],     al0, al1, al2, al3, bh0, bh1);
                        MMA16816(d[g][ga][np * 2 + 1], ah0, ah1, ah2, ah3, bh2, bh3);
                        MMA16816(d[g][ga][np * 2 + 1], ah0, ah1, ah2, ah3, bl2, bl3);
                        MMA16816(d[g][ga][np * 2 + 1], al0, al1, al2, al3, bh2, bh3);
                    }
                }
            }
        }

        // epilogue: thread owns rows {g, g+8} (g = lane>>2), col pair (lane&3)*2 per ntile
        int Rbase = t * 64 + rg * 16 + (lane >> 2);
#pragma unroll
        for (int nt = 0; nt < 4; nt++) {
            int c0 = cg * 32 + nt * 8 + (lane & 3) * 2;
#pragma unroll
            for (int p = 0; p < 2; p++) {
                int row = Rbase + p * 8;
                size_t base = (size_t)row * 64 + c0;
                float2 hv = *(const float2*)(Xc + base);
                float o[2];
                unsigned short oh[2], ol[2];
#pragma unroll
                for (int e = 0; e < 2; e++) {
                    int c = c0 + e;
                    int ie = p * 2 + e;
                    float rr = sigm(d[0][0][nt][ie] + d[1][0][nt][ie] + sB[c]);
                    float zz = sigm(d[0][1][nt][ie] + d[1][1][nt][ie] + sB[64 + c]);
                    float ng = tanhf(d[0][2][nt][ie] + sB[128 + c] +
                                     rr * (d[1][2][nt][ie] + sB[192 + c]));
                    float h = e ? hv.y : hv.x;
                    o[e] = (1.f - zz) * ng + zz * h;
                    __nv_bfloat16 bh, bl; split_bf(o[e], bh, bl);
                    oh[e] = bfb(bh); ol[e] = bfb(bl);
                }
                *(float2*)(Xn + base) = make_float2(o[0], o[1]);
                *(uint32_t*)((char*)nXH + base * 2) = (uint32_t)oh[0] | ((uint32_t)oh[1] << 16);
                *(uint32_t*)((char*)nXL + base * 2) = (uint32_t)ol[0] | ((uint32_t)ol[1] << 16);
            }
        }
        __syncthreads();
    }
}

// ---------------- attention + pooling (FFMA path) ----------------
#define ATT_TILES 21
#define SROW 68
__global__ void __launch_bounds__(512, 1)
k_att(const float* __restrict__ ai_b, const float* __restrict__ aj_b, int sel) {
    extern __shared__ float sm[];
    float* sAI = sm;
    float* sAJ = sm + 16384;
    float* sC  = sm + 32768;

    const float* Xf = g_X[sel];
    int tid = threadIdx.x, lane = tid & 31, warp = tid >> 5;
    int half = warp >> 3, k8 = warp & 7;

    for (int i = tid; i < 4096; i += 512) {
        ((float4*)sAI)[i] = ((const float4*)g_AIW)[i];
        ((float4*)sAJ)[i] = ((const float4*)g_AJW)[i];
    }
    float aib[2][2], ajb[2][2];
#pragma unroll
    for (int t = 0; t < 2; t++) {
        aib[t][0] = ai_b[64 * t + lane * 2];
        aib[t][1] = ai_b[64 * t + lane * 2 + 1];
        ajb[t][0] = aj_b[64 * t + lane * 2];
        ajb[t][1] = aj_b[64 * t + lane * 2 + 1];
    }
    float asum[4][2][2] = {};

    float4 pc[4];
    int tile0 = blockIdx.x * ATT_TILES;
    if (tile0 < NT64) {
#pragma unroll
        for (int iter = 0; iter < 4; iter++) {
            int k0 = (k8 + iter * 8) * 4;
            int row = tile0 * 64 + half * 32 + lane;
            pc[iter] = (k0 < 64)
                ? *(const float4*)(Xf   + row * CC + k0)
                : *(const float4*)(g_X0 + row * CC + k0 - 64);
        }
    }
    __syncthreads();
    if (tile0 < NT64) {
#pragma unroll
        for (int iter = 0; iter < 4; iter++) {
            int k0 = (k8 + iter * 8) * 4;
            int r = half * 32 + lane;
            sC[(k0 + 0) * SROW + r] = pc[iter].x;
            sC[(k0 + 1) * SROW + r] = pc[iter].y;
            sC[(k0 + 2) * SROW + r] = pc[iter].z;
            sC[(k0 + 3) * SROW + r] = pc[iter].w;
        }
    }
    __syncthreads();

    for (int it = 0; it < ATT_TILES; it++) {
        int tile = blockIdx.x * ATT_TILES + it;
        bool valid  = tile < NT64;
        bool nvalid = (it + 1 < ATT_TILES) && (tile + 1 < NT64);
        if (nvalid) {
#pragma unroll
            for (int iter = 0; iter < 4; iter++) {
                int k0 = (k8 + iter * 8) * 4;
                int row = (tile + 1) * 64 + half * 32 + lane;
                pc[iter] = (k0 < 64)
                    ? *(const float4*)(Xf   + row * CC + k0)
                    : *(const float4*)(g_X0 + row * CC + k0 - 64);
            }
        }
        if (valid) {
            float ai[4][2][2] = {};
            float aj[4][2][2] = {};
#pragma unroll 2
            for (int k = 0; k < 128; k++) {
                float4 c4 = *(const float4*)&sC[k * SROW + warp * 4];
                float2 i0 = *(const float2*)&sAI[k * 128 +      lane * 2];
                float2 i1 = *(const float2*)&sAI[k * 128 + 64 + lane * 2];
                float2 j0 = *(const float2*)&sAJ[k * 128 +      lane * 2];
                float2 j1 = *(const float2*)&sAJ[k * 128 + 64 + lane * 2];
                float cc[4] = {c4.x, c4.y, c4.z, c4.w};
                float iv[2][2] = {{i0.x, i0.y}, {i1.x, i1.y}};
                float jv[2][2] = {{j0.x, j0.y}, {j1.x, j1.y}};
#pragma unroll
                for (int nd = 0; nd < 4; nd++)
#pragma unroll
                    for (int t = 0; t < 2; t++)
#pragma unroll
                        for (int c2 = 0; c2 < 2; c2++) {
                            ai[nd][t][c2] += cc[nd] * iv[t][c2];
                            aj[nd][t][c2] += cc[nd] * jv[t][c2];
                        }
            }
#pragma unroll
            for (int nd = 0; nd < 4; nd++)
#pragma unroll
                for (int t = 0; t < 2; t++)
#pragma unroll
                    for (int c2 = 0; c2 < 2; c2++) {
                        float a = sigm(ai[nd][t][c2] + aib[t][c2]);
                        float r = aj[nd][t][c2] + ajb[t][c2];
                        r = r > 0.f ? r : 0.f;
                        asum[nd][t][c2] += a * r;
                    }
        }
        __syncthreads();
        if (nvalid) {
#pragma unroll
            for (int iter = 0; iter < 4; iter++) {
                int k0 = (k8 + iter * 8) * 4;
                int r = half * 32 + lane;
                sC[(k0 + 0) * SROW + r] = pc[iter].x;
                sC[(k0 + 1) * SROW + r] = pc[iter].y;
                sC[(k0 + 2) * SROW + r] = pc[iter].z;
                sC[(k0 + 3) * SROW + r] = pc[iter].w;
            }
        }
        __syncthreads();
    }

#pragma unroll
    for (int nd = 0; nd < 4; nd++)
#pragma unroll
        for (int t = 0; t < 2; t++)
#pragma unroll
            for (int c2 = 0; c2 < 2; c2++)
                sC[(warp * 4 + nd) * 128 + (t * 64 + lane * 2 + c2)] = asum[nd][t][c2];
    __syncthreads();
    {
        int i = tid;
        int b = i >> 7, j = i & 127;
        float s = 0.f;
#pragma unroll
        for (int w = 0; w < 16; w++) s += sC[(w * 4 + b) * 128 + j];
        atomicAdd(&g_POOL[b * 128 + j], s);
    }
}

// ---------------- final head ----------------
__global__ void k_head(const float* __restrict__ mlp_w, const float* __restrict__ mlp_b,
                       const float* __restrict__ cw, const float* __restrict__ cb,
                       float* __restrict__ out) {
    __shared__ float pooled[512];
    __shared__ float st[1024];
    int tid = threadIdx.x;
    for (int i = tid; i < 512; i += 256) pooled[i] = fmaxf(g_POOL[i], 0.f);
    __syncthreads();
    float acc[4] = {0.f, 0.f, 0.f, 0.f};
    for (int k = 0; k < 128; k++) {
        float w = mlp_w[tid * 128 + k];
#pragma unroll
        for (int b = 0; b < 4; b++) acc[b] += pooled[b * 128 + k] * w;
    }
    float mb = mlp_b[tid];
#pragma unroll
    for (int b = 0; b < 4; b++) st[b * 256 + tid] = fmaxf(acc[b] + mb, 0.f);
    __syncthreads();
    if (tid < 128) {
        int w = tid >> 5, lane = tid & 31;
        float s = 0.f;
        for (int k = lane; k < 256; k += 32) s += st[w * 256 + k] * cw[k];
#pragma unroll
        for (int off = 16; off; off >>= 1) s += __shfl_xor_sync(0xffffffffu, s, off);
        if (lane == 0) out[w] = s + cb[0];
    }
}

// ---------------- launch ----------------
extern "C" void kernel_launch(void* const* d_in, const int* in_sizes, int n_in,
                              void* d_out, int out_size) {
    const float* cov    = (const float*)d_in[0];
    const float* nodes  = (const float*)d_in[1];
    const int*   edges  = (const int*)  d_in[2];
    const int*   c2l    = (const int*)  d_in[3];
    const float* ggc    = (const float*)d_in[4];
    const float* w_ih   = (const float*)d_in[5];
    const float* w_hh   = (const float*)d_in[6];
    const float* b_ih   = (const float*)d_in[7];
    const float* b_hh   = (const float*)d_in[8];
    const float* ai_w   = (const float*)d_in[9];
    const float* ai_b   = (const float*)d_in[10];
    const float* aj_w   = (const float*)d_in[11];
    const float* aj_b   = (const float*)d_in[12];
    const float* mlp_w  = (const float*)d_in[13];
    const float* mlp_b  = (const float*)d_in[14];
    const float* cw     = (const float*)d_in[15];
    const float* cb     = (const float*)d_in[16];
    float* out = (float*)d_out;

    const int smem_att = 41472 * 4;     // 165888 B
    cudaFuncSetAttribute(k_gru_mma, cudaFuncAttributeMaxDynamicSharedMemorySize, SMEM_MMA);
    cudaFuncSetAttribute(k_att, cudaFuncAttributeMaxDynamicSharedMemorySize, smem_att);

    k_prep_W2<<<288, 256>>>(ggc, w_ih, w_hh);
    k_prep_T<<<128, 256>>>(ai_w, aj_w);
    k_init<<<NN, 256>>>(nodes);
    k_cov<<<(BB * NLBL + 255) / 256, 256>>>(cov, c2l);

    k_zero_cnt<<<(NN + 255) / 256, 256>>>();
    k_hist<<<(EE + 255) / 256, 256>>>(edges);
    k_scan<<<1, 1024>>>();
    k_fill<<<(EE + 255) / 256, 256>>>(edges);

    int sel = 0;
    for (int l = 0; l < 5; l++) {
        k_gather<<<(NN * 64 + 255) / 256, 256>>>(sel);
        k_gru_mma<<<148, 256, SMEM_MMA>>>(b_ih, b_hh, l, sel);
        sel ^= 1;
    }

    k_zero_pool<<<2, 256>>>();
    k_att<<<(NT64 + ATT_TILES - 1) / ATT_TILES, 512, smem_att>>>(ai_b, aj_b, sel);
    k_head<<<1, 256>>>(mlp_w, mlp_b, cw, cb, out);
}

// round 17
// speedup vs baseline: 1.8288x; 1.0909x over previous
#include <cuda_runtime.h>
#include <cuda_bf16.h>
#include <cstdint>
#include <math.h>

#define BB   4
#define NN   50000
#define CC   64
#define EE   800000
#define NLBL 10000
#define RR   (NN*BB)        /* 200000 GEMM rows (node,batch) */
#define ROWF (BB*CC)        /* 256 floats per node across batches */
#define NT64 (RR/64)        /* 3125 64-row tiles */
#define PADR 200064

// ---------------- device scratch ----------------
__device__ float g_X[2][RR*CC];          // ping-pong node state fp32
__device__ float g_X0[RR*CC];            // initial features (fp32, gru h-path)
__device__ float g_POOL[512];
// split-bf16 planes (hi/lo) for HMMA GEMMs
__device__ __nv_bfloat16 g_AGH[PADR*CC], g_AGL[PADR*CC];         // AGG
__device__ __nv_bfloat16 g_XPH[2][PADR*CC], g_XPL[2][PADR*CC];   // X ping-pong
__device__ __nv_bfloat16 g_X0H[RR*CC], g_X0L[RR*CC];             // X0 split
__device__ __nv_bfloat16 g_P2H[5*192*64], g_P2L[5*192*64];       // P^T [l][j][k]
__device__ __nv_bfloat16 g_W2H[192*64],  g_W2L[192*64];          // w_hh [j][k]
__device__ __nv_bfloat16 g_AIH[128*128], g_AIL[128*128];         // ai_w [j][k] split
__device__ __nv_bfloat16 g_AJH[128*128], g_AJL[128*128];         // aj_w [j][k] split
// CSR by destination
__device__ int   g_cnt[NN];
__device__ int   g_off[NN];
__device__ int   g_cur[NN];
__device__ int   g_csr[EE];

__device__ __forceinline__ float sigm(float v) { return 1.0f / (1.0f + expf(-v)); }

__device__ __forceinline__ void split_bf(float v, __nv_bfloat16& h, __nv_bfloat16& l) {
    h = __float2bfloat16_rn(v);
    l = __float2bfloat16_rn(v - __bfloat162float(h));
}
__device__ __forceinline__ unsigned short bfb(__nv_bfloat16 v) { return __bfloat16_as_ushort(v); }

__device__ __forceinline__ uint32_t smem_u32(const void* p) {
    uint32_t a;
    asm("{ .reg .u64 t; cvta.to.shared.u64 t, %1; cvt.u32.u64 %0, t; }" : "=r"(a) : "l"(p));
    return a;
}

#define LDSM4(r0, r1, r2, r3, addr) \
    asm volatile("ldmatrix.sync.aligned.m8n8.x4.shared.b16 {%0,%1,%2,%3}, [%4];" \
        : "=r"(r0), "=r"(r1), "=r"(r2), "=r"(r3) : "r"(addr))

#define MMA16816(d, a0, a1, a2, a3, b0, b1) \
    asm volatile("mma.sync.aligned.m16n8k16.row.col.f32.bf16.bf16.f32 " \
        "{%0,%1,%2,%3}, {%4,%5,%6,%7}, {%8,%9}, {%0,%1,%2,%3};" \
        : "+f"((d)[0]), "+f"((d)[1]), "+f"((d)[2]), "+f"((d)[3]) \
        : "r"(a0), "r"(a1), "r"(a2), "r"(a3), "r"(b0), "r"(b1))

// ---------------- prep kernels ----------------
__global__ void k_prep_W2(const float* __restrict__ ggc, const float* __restrict__ w_ih,
                          const float* __restrict__ w_hh) {
    int idx = blockIdx.x * 256 + threadIdx.x;
    if (idx < 5 * 192 * 64) {
        int l = idx / 12288, rem = idx % 12288;
        int j = rem / 64, k = rem % 64;
        const float* a = ggc + (l * 64 + k) * 64;
        const float* w = w_ih + j * 64;
        float s = 0.f;
#pragma unroll 8
        for (int c = 0; c < 64; c++) s += a[c] * w[c];
        __nv_bfloat16 h, lo; split_bf(s, h, lo);
        g_P2H[idx] = h; g_P2L[idx] = lo;
    } else if (idx < 5 * 12288 + 12288) {
        int i = idx - 61440;
        __nv_bfloat16 h, lo; split_bf(w_hh[i], h, lo);
        g_W2H[i] = h; g_W2L[i] = lo;
    }
}

// elementwise split of ai_w/aj_w (consumed [j][k] row-major = B col-major fragment)
__global__ void k_prep_ATT(const float* __restrict__ ai_w, const float* __restrict__ aj_w) {
    int idx = blockIdx.x * 256 + threadIdx.x;
    if (idx >= 16384) return;
    __nv_bfloat16 h, l;
    split_bf(ai_w[idx], h, l);
    g_AIH[idx] = h; g_AIL[idx] = l;
    split_bf(aj_w[idx], h, l);
    g_AJH[idx] = h; g_AJL[idx] = l;
}

__global__ void k_init(const float* __restrict__ nodes) {
    int n = blockIdx.x;
    int t = threadIdx.x;
    int c = t & 63;
    float v = (c < 63) ? nodes[n * 63 + c] : 0.f;
    int idx = n * ROWF + t;
    g_X0[idx] = v;
    g_X[0][idx] = v;
    __nv_bfloat16 h, l; split_bf(v, h, l);
    g_XPH[0][idx] = h; g_XPL[0][idx] = l;
    g_X0H[idx] = h;    g_X0L[idx] = l;
}

__global__ void k_cov(const float* __restrict__ cov, const int* __restrict__ c2l) {
    int idx = blockIdx.x * 256 + threadIdx.x;
    if (idx >= BB * NLBL) return;
    int b = idx / NLBL, j = idx % NLBL;
    int lbl = c2l[j];
    float v = cov[idx];
    int pos = lbl * ROWF + b * 64 + 63;
    g_X0[pos] = v;
    g_X[0][pos] = v;
    __nv_bfloat16 h, l; split_bf(v, h, l);
    g_XPH[0][pos] = h; g_XPL[0][pos] = l;
    g_X0H[pos] = h;    g_X0L[pos] = l;
}

__global__ void k_zero_pool() {
    int idx = blockIdx.x * 256 + threadIdx.x;
    if (idx < 512) g_POOL[idx] = 0.f;
}

// ---------------- CSR build ----------------
__global__ void k_zero_cnt() {
    int i = blockIdx.x * 256 + threadIdx.x;
    if (i < NN) g_cnt[i] = 0;
}
__global__ void k_hist(const int* __restrict__ edges) {
    int e = blockIdx.x * 256 + threadIdx.x;
    if (e < EE) atomicAdd(&g_cnt[edges[EE + e]], 1);
}
__global__ void __launch_bounds__(1024, 1) k_scan() {
    __shared__ int sp[1024];
    const int CH = (NN + 1023) / 1024;
    int t = threadIdx.x;
    int b0 = t * CH;
    int s = 0;
    for (int i = 0; i < CH; i++) { int n = b0 + i; if (n < NN) s += g_cnt[n]; }
    sp[t] = s;
    __syncthreads();
    for (int off = 1; off < 1024; off <<= 1) {
        int v = (t >= off) ? sp[t - off] : 0;
        __syncthreads();
        sp[t] += v;
        __syncthreads();
    }
    int base = sp[t] - s;
    for (int i = 0; i < CH; i++) {
        int n = b0 + i;
        if (n < NN) { g_off[n] = base; g_cur[n] = base; base += g_cnt[n]; }
    }
}
__global__ void k_fill(const int* __restrict__ edges) {
    int e = blockIdx.x * 256 + threadIdx.x;
    if (e >= EE) return;
    int dst = edges[EE + e];
    int pos = atomicAdd(&g_cur[dst], 1);
    g_csr[pos] = edges[e];
}

// ---------------- gather: AGG planes (split bf16) = sum of X rows ----------------
__global__ void __launch_bounds__(256, 8) k_gather(int sel) {
    unsigned gid = blockIdx.x * 256u + threadIdx.x;
    int node = gid >> 6;
    int q = (gid & 63) * 4;
    if (node >= NN) return;
    const float* __restrict__ X = g_X[sel];
    int beg = g_off[node];
    int cnt = g_cnt[node];
    float4 acc = make_float4(0.f, 0.f, 0.f, 0.f);
    int j = 0;
    for (; j + 4 <= cnt; j += 4) {
        int i0 = g_csr[beg + j];
        int i1 = g_csr[beg + j + 1];
        int i2 = g_csr[beg + j + 2];
        int i3 = g_csr[beg + j + 3];
        const float4 v0 = *(const float4*)(X + i0 * ROWF + q);
        const float4 v1 = *(const float4*)(X + i1 * ROWF + q);
        const float4 v2 = *(const float4*)(X + i2 * ROWF + q);
        const float4 v3 = *(const float4*)(X + i3 * ROWF + q);
        acc.x += v0.x + v1.x + v2.x + v3.x;
        acc.y += v0.y + v1.y + v2.y + v3.y;
        acc.z += v0.z + v1.z + v2.z + v3.z;
        acc.w += v0.w + v1.w + v2.w + v3.w;
    }
    for (; j < cnt; j++) {
        int i0 = g_csr[beg + j];
        const float4 v0 = *(const float4*)(X + i0 * ROWF + q);
        acc.x += v0.x; acc.y += v0.y; acc.z += v0.z; acc.w += v0.w;
    }
    float vv[4] = {acc.x, acc.y, acc.z, acc.w};
    unsigned short hs[4], ls[4];
#pragma unroll
    for (int i = 0; i < 4; i++) {
        __nv_bfloat16 h, l; split_bf(vv[i], h, l);
        hs[i] = bfb(h); ls[i] = bfb(l);
    }
    size_t po = (size_t)node * ROWF + q;
    uint2 uh, ul;
    uh.x = (uint32_t)hs[0] | ((uint32_t)hs[1] << 16);
    uh.y = (uint32_t)hs[2] | ((uint32_t)hs[3] << 16);
    ul.x = (uint32_t)ls[0] | ((uint32_t)ls[1] << 16);
    ul.y = (uint32_t)ls[2] | ((uint32_t)ls[3] << 16);
    *(uint2*)((char*)g_AGH + po * 2) = uh;
    *(uint2*)((char*)g_AGL + po * 2) = ul;
}

// ---------------- HMMA (mma.sync bf16 split) GGC+GRU layer ----------------
#define OFS_BIAS 0
#define OFS_AGH  1024
#define OFS_AGL  10240
#define OFS_XH   19456
#define OFS_XL   28672
#define OFS_PH   37888
#define OFS_PL   65536
#define OFS_WH   93184
#define OFS_WL   120832
#define SMEM_MMA 148480

__global__ void __launch_bounds__(256, 1)
k_gru_mma(const float* __restrict__ b_ih, const float* __restrict__ b_hh, int layer, int sel) {
    extern __shared__ char smem[];
    uint32_t sb = smem_u32(smem);
    int tid = threadIdx.x, lane = tid & 31, wid = tid >> 5;
    int rg = wid & 3, cg = wid >> 2;

    float* sB = (float*)(smem + OFS_BIAS);
    if (tid < 64) {
        sB[tid]       = b_ih[tid]       + b_hh[tid];
        sB[64 + tid]  = b_ih[64 + tid]  + b_hh[64 + tid];
        sB[128 + tid] = b_ih[128 + tid];
        sB[192 + tid] = b_hh[128 + tid];
    }
    {
        const uint4* s0 = (const uint4*)(g_P2H + layer * 12288);
        const uint4* s1 = (const uint4*)(g_P2L + layer * 12288);
        const uint4* s2 = (const uint4*)g_W2H;
        const uint4* s3 = (const uint4*)g_W2L;
        for (int i = tid; i < 1536; i += 256) {
            int row = i >> 3, ch = i & 7;
            int dst = row * 144 + ch * 16;
            *(uint4*)(smem + OFS_PH + dst) = s0[i];
            *(uint4*)(smem + OFS_PL + dst) = s1[i];
            *(uint4*)(smem + OFS_WH + dst) = s2[i];
            *(uint4*)(smem + OFS_WL + dst) = s3[i];
        }
    }
    __syncthreads();

    const float* Xc = g_X[sel];
    float*       Xn = g_X[sel ^ 1];
    const __nv_bfloat16* pXH = g_XPH[sel];
    const __nv_bfloat16* pXL = g_XPL[sel];
    __nv_bfloat16* nXH = g_XPH[sel ^ 1];
    __nv_bfloat16* nXL = g_XPL[sel ^ 1];

    int lr = lane & 7, lsel = lane >> 3;
    uint32_t rowoff_a = (uint32_t)(lr + ((lsel & 1) ? 8 : 0)) * 144 + ((lsel >> 1) & 1) * 16;
    uint32_t rowoff_b = (uint32_t)(lr + ((lsel >= 2) ? 8 : 0)) * 144 + (lsel & 1) * 16;

    uint32_t aBase[2][2] = {{sb + OFS_AGH, sb + OFS_AGL}, {sb + OFS_XH, sb + OFS_XL}};
    uint32_t wBase[2][2] = {{sb + OFS_PH,  sb + OFS_PL},  {sb + OFS_WH, sb + OFS_WL}};

    for (int t = blockIdx.x; t < NT64; t += 148) {
        {
            const uint4* s0 = (const uint4*)(g_AGH + (size_t)t * 4096);
            const uint4* s1 = (const uint4*)(g_AGL + (size_t)t * 4096);
            const uint4* s2 = (const uint4*)(pXH + (size_t)t * 4096);
            const uint4* s3 = (const uint4*)(pXL + (size_t)t * 4096);
            for (int i = tid; i < 512; i += 256) {
                int row = i >> 3, ch = i & 7;
                int dst = row * 144 + ch * 16;
                *(uint4*)(smem + OFS_AGH + dst) = s0[i];
                *(uint4*)(smem + OFS_AGL + dst) = s1[i];
                *(uint4*)(smem + OFS_XH + dst) = s2[i];
                *(uint4*)(smem + OFS_XL + dst) = s3[i];
            }
        }
        __syncthreads();

        float d[2][3][4][4];
#pragma unroll
        for (int g = 0; g < 2; g++)
#pragma unroll
            for (int ga = 0; ga < 3; ga++)
#pragma unroll
                for (int nt = 0; nt < 4; nt++)
#pragma unroll
                    for (int e = 0; e < 4; e++) d[g][ga][nt][e] = 0.f;

        uint32_t R0b = (uint32_t)(rg * 16) * 144;
#pragma unroll
        for (int ks = 0; ks < 4; ks++) {
            uint32_t kb = ks * 32;
#pragma unroll
            for (int g = 0; g < 2; g++) {
                uint32_t ah0, ah1, ah2, ah3, al0, al1, al2, al3;
                LDSM4(ah0, ah1, ah2, ah3, aBase[g][0] + R0b + kb + rowoff_a);
                LDSM4(al0, al1, al2, al3, aBase[g][1] + R0b + kb + rowoff_a);
#pragma unroll
                for (int ga = 0; ga < 3; ga++) {
#pragma unroll
                    for (int np = 0; np < 2; np++) {
                        uint32_t J0b = (uint32_t)(ga * 64 + cg * 32 + np * 16) * 144;
                        uint32_t bh0, bh1, bh2, bh3, bl0, bl1, bl2, bl3;
                        LDSM4(bh0, bh1, bh2, bh3, wBase[g][0] + J0b + kb + rowoff_b);
                        LDSM4(bl0, bl1, bl2, bl3, wBase[g][1] + J0b + kb + rowoff_b);
                        MMA16816(d[g][ga][np * 2],     ah0, ah1, ah2, ah3, bh0, bh1);
                        MMA16816(d[g][ga][np * 2],     ah0, ah1, ah2, ah3, bl0, bl1);
                        MMA16816(d[g][ga][np * 2],     al0, al1, al2, al3, bh0, bh1);
                        MMA16816(d[g][ga][np * 2 + 1], ah0, ah1, ah2, ah3, bh2, bh3);
                        MMA16816(d[g][ga][np * 2 + 1], ah0, ah1, ah2, ah3, bl2, bl3);
                        MMA16816(d[g][ga][np * 2 + 1], al0, al1, al2, al3, bh2, bh3);
                    }
                }
            }
        }

        int Rbase = t * 64 + rg * 16 + (lane >> 2);
#pragma unroll
        for (int nt = 0; nt < 4; nt++) {
            int c0 = cg * 32 + nt * 8 + (lane & 3) * 2;
#pragma unroll
            for (int p = 0; p < 2; p++) {
                int row = Rbase + p * 8;
                size_t base = (size_t)row * 64 + c0;
                float2 hv = *(const float2*)(Xc + base);
                float o[2];
                unsigned short oh[2], ol[2];
#pragma unroll
                for (int e = 0; e < 2; e++) {
                    int c = c0 + e;
                    int ie = p * 2 + e;
                    float rr = sigm(d[0][0][nt][ie] + d[1][0][nt][ie] + sB[c]);
                    float zz = sigm(d[0][1][nt][ie] + d[1][1][nt][ie] + sB[64 + c]);
                    float ng = tanhf(d[0][2][nt][ie] + sB[128 + c] +
                                     rr * (d[1][2][nt][ie] + sB[192 + c]));
                    float h = e ? hv.y : hv.x;
                    o[e] = (1.f - zz) * ng + zz * h;
                    __nv_bfloat16 bh, bl; split_bf(o[e], bh, bl);
                    oh[e] = bfb(bh); ol[e] = bfb(bl);
                }
                *(float2*)(Xn + base) = make_float2(o[0], o[1]);
                *(uint32_t*)((char*)nXH + base * 2) = (uint32_t)oh[0] | ((uint32_t)oh[1] << 16);
                *(uint32_t*)((char*)nXL + base * 2) = (uint32_t)ol[0] | ((uint32_t)ol[1] << 16);
            }
        }
        __syncthreads();
    }
}

// ---------------- HMMA attention + pooling ----------------
// cat = [x, x0] (K=128 -> 8 k-steps). ai/aj gemms 3-term split-bf16.
// 8 warps: rg=wid&3 -> 16 rows, cg=wid>>2 -> 64 of 128 cols.
// Thread batch is invariant: (lane>>2)&3. Pool reduced via shfl+smem, 512 atomics/CTA.
#define OFA_BIAS 0
#define OFA_CH   1024
#define OFA_CL   18432
#define OFA_IH   35840
#define OFA_IL   70656
#define OFA_JH   105472
#define OFA_JL   140288
#define SMEM_ATT 175104

__global__ void __launch_bounds__(256, 1)
k_att_mma(const float* __restrict__ ai_b, const float* __restrict__ aj_b, int sel) {
    extern __shared__ char smem[];
    uint32_t sb = smem_u32(smem);
    int tid = threadIdx.x, lane = tid & 31, wid = tid >> 5;
    int rg = wid & 3, cg = wid >> 2;

    float* sBias = (float*)(smem + OFA_BIAS);     // [0:128) ai_b, [128:256) aj_b
    if (tid < 128) {
        sBias[tid] = ai_b[tid];
        sBias[128 + tid] = aj_b[tid];
    }
    // weights: 128 rows x 256B (16 chunks), padded stride 272B
    {
        const uint4* s0 = (const uint4*)g_AIH;
        const uint4* s1 = (const uint4*)g_AIL;
        const uint4* s2 = (const uint4*)g_AJH;
        const uint4* s3 = (const uint4*)g_AJL;
        for (int i = tid; i < 2048; i += 256) {
            int row = i >> 4, ch = i & 15;
            int dst = row * 272 + ch * 16;
            *(uint4*)(smem + OFA_IH + dst) = s0[i];
            *(uint4*)(smem + OFA_IL + dst) = s1[i];
            *(uint4*)(smem + OFA_JH + dst) = s2[i];
            *(uint4*)(smem + OFA_JL + dst) = s3[i];
        }
    }
    __syncthreads();

    const __nv_bfloat16* pXH = g_XPH[sel];
    const __nv_bfloat16* pXL = g_XPL[sel];

    int lr = lane & 7, lsel = lane >> 3;
    uint32_t rowoff_a = (uint32_t)(lr + ((lsel & 1) ? 8 : 0)) * 272 + ((lsel >> 1) & 1) * 16;
    uint32_t rowoff_b = (uint32_t)(lr + ((lsel >= 2) ? 8 : 0)) * 272 + (lsel & 1) * 16;

    uint32_t wBase[2][2] = {{sb + OFA_IH, sb + OFA_IL}, {sb + OFA_JH, sb + OFA_JL}};

    float aib[4][2][2], ajb[4][2][2];
#pragma unroll
    for (int np = 0; np < 4; np++)
#pragma unroll
        for (int pp = 0; pp < 2; pp++)
#pragma unroll
            for (int e = 0; e < 2; e++) {
                int c = cg * 64 + np * 16 + pp * 8 + (lane & 3) * 2 + e;
                aib[np][pp][e] = sBias[c];
                ajb[np][pp][e] = sBias[128 + c];
            }

    float acc[4][2][2] = {};   // pooled a*r sums, thread-fixed batch

    for (int t = blockIdx.x; t < NT64; t += 148) {
        // stage cat tile: 64 rows x 128 halves hi/lo; chunks 0-7 from X, 8-15 from X0
        {
            const uint4* xh = (const uint4*)(pXH + (size_t)t * 4096);
            const uint4* xl = (const uint4*)(pXL + (size_t)t * 4096);
            const uint4* zh = (const uint4*)(g_X0H + (size_t)t * 4096);
            const uint4* zl = (const uint4*)(g_X0L + (size_t)t * 4096);
            for (int i = tid; i < 1024; i += 256) {
                int row = i >> 4, ch = i & 15;
                int dst = row * 272 + ch * 16;
                int src = row * 8 + (ch & 7);
                if (ch < 8) {
                    *(uint4*)(smem + OFA_CH + dst) = xh[src];
                    *(uint4*)(smem + OFA_CL + dst) = xl[src];
                } else {
                    *(uint4*)(smem + OFA_CH + dst) = zh[src];
                    *(uint4*)(smem + OFA_CL + dst) = zl[src];
                }
            }
        }
        __syncthreads();

        float d[2][4][2][4];   // [gemm][np][ntile pair][4]
#pragma unroll
        for (int g = 0; g < 2; g++)
#pragma unroll
            for (int np = 0; np < 4; np++)
#pragma unroll
                for (int pp = 0; pp < 2; pp++)
#pragma unroll
                    for (int e = 0; e < 4; e++) d[g][np][pp][e] = 0.f;

        uint32_t R0b = (uint32_t)(rg * 16) * 272;
#pragma unroll
        for (int ks = 0; ks < 8; ks++) {
            uint32_t kb = ks * 32;
            uint32_t ah0, ah1, ah2, ah3, al0, al1, al2, al3;
            LDSM4(ah0, ah1, ah2, ah3, sb + OFA_CH + R0b + kb + rowoff_a);
            LDSM4(al0, al1, al2, al3, sb + OFA_CL + R0b + kb + rowoff_a);
#pragma unroll
            for (int g = 0; g < 2; g++) {
#pragma unroll
                for (int np = 0; np < 4; np++) {
                    uint32_t J0b = (uint32_t)(cg * 64 + np * 16) * 272;
                    uint32_t bh0, bh1, bh2, bh3, bl0, bl1, bl2, bl3;
                    LDSM4(bh0, bh1, bh2, bh3, wBase[g][0] + J0b + kb + rowoff_b);
                    LDSM4(bl0, bl1, bl2, bl3, wBase[g][1] + J0b + kb + rowoff_b);
                    MMA16816(d[g][np][0], ah0, ah1, ah2, ah3, bh0, bh1);
                    MMA16816(d[g][np][0], ah0, ah1, ah2, ah3, bl0, bl1);
                    MMA16816(d[g][np][0], al0, al1, al2, al3, bh0, bh1);
                    MMA16816(d[g][np][1], ah0, ah1, ah2, ah3, bh2, bh3);
                    MMA16816(d[g][np][1], ah0, ah1, ah2, ah3, bl2, bl3);
                    MMA16816(d[g][np][1], al0, al1, al2, al3, bh2, bh3);
                }
            }
        }

        // pooled epilogue: sum sigmoid(ai)*relu(aj) over this warp's 2 owned rows
#pragma unroll
        for (int np = 0; np < 4; np++)
#pragma unroll
            for (int pp = 0; pp < 2; pp++)
#pragma unroll
                for (int p = 0; p < 2; p++)
#pragma unroll
                    for (int e = 0; e < 2; e++) {
                        int ie = p * 2 + e;
                        float a = sigm(d[0][np][pp][ie] + aib[np][pp][e]);
                        float r = d[1][np][pp][ie] + ajb[np][pp][e];
                        r = r > 0.f ? r : 0.f;
                        acc[np][pp][e] += a * r;
                    }
        __syncthreads();
    }

    // reduce: lane & lane^16 share (batch,col)
#pragma unroll
    for (int np = 0; np < 4; np++)
#pragma unroll
        for (int pp = 0; pp < 2; pp++)
#pragma unroll
            for (int e = 0; e < 2; e++)
                acc[np][pp][e] += __shfl_xor_sync(0xffffffffu, acc[np][pp][e], 16);

    float* red = (float*)(smem + OFA_CH);   // 8 warps x 16 lanes x 16 vals = 2048 f
    if (lane < 16) {
#pragma unroll
        for (int np = 0; np < 4; np++)
#pragma unroll
            for (int pp = 0; pp < 2; pp++)
#pragma unroll
                for (int e = 0; e < 2; e++)
                    red[wid * 256 + lane * 16 + np * 4 + pp * 2 + e] = acc[np][pp][e];
    }
    __syncthreads();
    for (int o = tid; o < 512; o += 256) {
        int b = o >> 7, col = o & 127;
        int cgo = col >> 6, w = col & 63;
        int np = w >> 4, pp = (w >> 3) & 1, cp = (w >> 1) & 3, e = w & 1;
        float s = 0.f;
#pragma unroll
        for (int r = 0; r < 4; r++)
            s += red[(cgo * 4 + r) * 256 + (b * 4 + cp) * 16 + np * 4 + pp * 2 + e];
        atomicAdd(&g_POOL[b * 128 + col], s);
    }
}

// ---------------- final head ----------------
__global__ void k_head(const float* __restrict__ mlp_w, const float* __restrict__ mlp_b,
                       const float* __restrict__ cw, const float* __restrict__ cb,
                       float* __restrict__ out) {
    __shared__ float pooled[512];
    __shared__ float st[1024];
    int tid = threadIdx.x;
    for (int i = tid; i < 512; i += 256) pooled[i] = fmaxf(g_POOL[i], 0.f);
    __syncthreads();
    float acc[4] = {0.f, 0.f, 0.f, 0.f};
    for (int k = 0; k < 128; k++) {
        float w = mlp_w[tid * 128 + k];
#pragma unroll
        for (int b = 0; b < 4; b++) acc[b] += pooled[b * 128 + k] * w;
    }
    float mb = mlp_b[tid];
#pragma unroll
    for (int b = 0; b < 4; b++) st[b * 256 + tid] = fmaxf(acc[b] + mb, 0.f);
    __syncthreads();
    if (tid < 128) {
        int w = tid >> 5, lane = tid & 31;
        float s = 0.f;
        for (int k = lane; k < 256; k += 32) s += st[w * 256 + k] * cw[k];
#pragma unroll
        for (int off = 16; off; off >>= 1) s += __shfl_xor_sync(0xffffffffu, s, off);
        if (lane == 0) out[w] = s + cb[0];
    }
}

// ---------------- launch ----------------
extern "C" void kernel_launch(void* const* d_in, const int* in_sizes, int n_in,
                              void* d_out, int out_size) {
    const float* cov    = (const float*)d_in[0];
    const float* nodes  = (const float*)d_in[1];
    const int*   edges  = (const int*)  d_in[2];
    const int*   c2l    = (const int*)  d_in[3];
    const float* ggc    = (const float*)d_in[4];
    const float* w_ih   = (const float*)d_in[5];
    const float* w_hh   = (const float*)d_in[6];
    const float* b_ih   = (const float*)d_in[7];
    const float* b_hh   = (const float*)d_in[8];
    const float* ai_w   = (const float*)d_in[9];
    const float* ai_b   = (const float*)d_in[10];
    const float* aj_w   = (const float*)d_in[11];
    const float* aj_b   = (const float*)d_in[12];
    const float* mlp_w  = (const float*)d_in[13];
    const float* mlp_b  = (const float*)d_in[14];
    const float* cw     = (const float*)d_in[15];
    const float* cb     = (const float*)d_in[16];
    float* out = (float*)d_out;

    cudaFuncSetAttribute(k_gru_mma, cudaFuncAttributeMaxDynamicSharedMemorySize, SMEM_MMA);
    cudaFuncSetAttribute(k_att_mma, cudaFuncAttributeMaxDynamicSharedMemorySize, SMEM_ATT);

    k_prep_W2<<<288, 256>>>(ggc, w_ih, w_hh);
    k_prep_ATT<<<64, 256>>>(ai_w, aj_w);
    k_init<<<NN, 256>>>(nodes);
    k_cov<<<(BB * NLBL + 255) / 256, 256>>>(cov, c2l);

    k_zero_cnt<<<(NN + 255) / 256, 256>>>();
    k_hist<<<(EE + 255) / 256, 256>>>(edges);
    k_scan<<<1, 1024>>>();
    k_fill<<<(EE + 255) / 256, 256>>>(edges);

    int sel = 0;
    for (int l = 0; l < 5; l++) {
        k_gather<<<(NN * 64 + 255) / 256, 256>>>(sel);
        k_gru_mma<<<148, 256, SMEM_MMA>>>(b_ih, b_hh, l, sel);
        sel ^= 1;
    }

    k_zero_pool<<<2, 256>>>();
    k_att_mma<<<148, 256, SMEM_ATT>>>(ai_b, aj_b, sel);
    k_head<<<1, 256>>>(mlp_w, mlp_b, cw, cb, out);
}